// round 13
// baseline (speedup 1.0000x reference)
#include <cuda_runtime.h>
#include <cuda_bf16.h>
#include <cuda_fp16.h>
#include <cstdint>

#define BATCH 4
#define SEQ   2048
#define DIM   1024
#define NORM_FACT 0.03125f   // 1/sqrt(1024), applied POST-softmax per reference

typedef __nv_bfloat16 bf16;

// ---------------------------------------------------------------------------
// Scratch (allocation-free rule: __device__ globals).
// Q/K pre-split bf16 hi/lo (3-term path); x/Wv/V/P fp16 (1-term paths).
// ---------------------------------------------------------------------------
#define NX  ((size_t)BATCH * SEQ * DIM)   // 8M
#define NW  ((size_t)DIM * DIM)           // 1M
#define NP  ((size_t)BATCH * SEQ * SEQ)   // 16M

__device__ __align__(256) bf16 g_xh[NX],  g_xl[NX];
__device__ __align__(256) bf16 g_Wqh[NW], g_Wql[NW];
__device__ __align__(256) bf16 g_Wkh[NW], g_Wkl[NW];
__device__ __align__(256) bf16 g_Qh[NX],  g_Ql[NX];
__device__ __align__(256) bf16 g_Kh[NX],  g_Kl[NX];
__device__ __align__(256) __half g_xf[NX];
__device__ __align__(256) __half g_Wvf[NW];
__device__ __align__(256) __half g_Vf[NX];
__device__ __align__(256) __half g_Vtf[NX];
__device__ __align__(256) __half g_Pf[NP];
__device__ __align__(256) float  g_P[NP];

// ---------------------------------------------------------------------------
// Smem layouts. Row stride 80 B -> ldmatrix conflict-free, cp.async 16B-aligned.
// ---------------------------------------------------------------------------
#define ROWB   80
#define TILEB  (128 * ROWB)          // 10240
#define STAGE  (4 * TILEB)           // 40960
#define SMEM_TOTAL (2 * STAGE)       // 81920
#define STAV   (2 * TILEB)           // 20480
#define SMEM_AV (2 * STAV)           // 40960

extern __shared__ char dsm[];

__device__ __forceinline__ uint32_t smem_u32(const void* p) {
    uint32_t a;
    asm("{ .reg .u64 t; cvta.to.shared.u64 t, %1; cvt.u32.u64 %0, t; }"
        : "=r"(a) : "l"(p));
    return a;
}

#define CPA16(dst, src) \
    asm volatile("cp.async.cg.shared.global [%0], [%1], 16;" :: "r"(dst), "l"(src))
#define CPA_COMMIT() asm volatile("cp.async.commit_group;" ::: "memory")
#define CPA_WAIT0()  asm volatile("cp.async.wait_group 0;" ::: "memory")

#define LDSM4(R, addr)                                                        \
    asm volatile("ldmatrix.sync.aligned.m8n8.x4.shared.b16 {%0,%1,%2,%3}, [%4];" \
                 : "=r"((R)[0]), "=r"((R)[1]), "=r"((R)[2]), "=r"((R)[3])     \
                 : "r"(addr))

#define MMA(cc, A, b0, b1)                                                    \
    asm volatile("mma.sync.aligned.m16n8k16.row.col.f32.bf16.bf16.f32 "       \
                 "{%0,%1,%2,%3},{%4,%5,%6,%7},{%8,%9},{%0,%1,%2,%3};"         \
                 : "+f"((cc)[0]), "+f"((cc)[1]), "+f"((cc)[2]), "+f"((cc)[3]) \
                 : "r"((A)[0]), "r"((A)[1]), "r"((A)[2]), "r"((A)[3]),        \
                   "r"(b0), "r"(b1))

#define MMA_F16(cc, A, b0, b1)                                                \
    asm volatile("mma.sync.aligned.m16n8k16.row.col.f32.f16.f16.f32 "         \
                 "{%0,%1,%2,%3},{%4,%5,%6,%7},{%8,%9},{%0,%1,%2,%3};"         \
                 : "+f"((cc)[0]), "+f"((cc)[1]), "+f"((cc)[2]), "+f"((cc)[3]) \
                 : "r"((A)[0]), "r"((A)[1]), "r"((A)[2]), "r"((A)[3]),        \
                   "r"(b0), "r"(b1))

__device__ __forceinline__ uint32_t pk(bf16 a, bf16 b) {
    return (uint32_t)__bfloat16_as_ushort(a) | ((uint32_t)__bfloat16_as_ushort(b) << 16);
}

__device__ __forceinline__ uint32_t pkh(float a, float b) {
    __half2 h = __floats2half2_rn(a, b);
    return *(uint32_t*)&h;
}

__device__ __forceinline__ void split1(float v, bf16& h, bf16& l) {
    h = __float2bfloat16_rn(v);
    l = __float2bfloat16_rn(v - __bfloat162float(h));
}

// ---------------------------------------------------------------------------
// 3-term split-precision NT GEMM body (validated R7 structure).
// ---------------------------------------------------------------------------
__device__ __forceinline__
void gemm_body(const bf16* __restrict__ Ah, const bf16* __restrict__ Al,
               const bf16* __restrict__ Bh, const bf16* __restrict__ Bl,
               const float* __restrict__ bias,
               float* __restrict__ Cf, bf16* __restrict__ Ch, bf16* __restrict__ Cl,
               int M, int N, int K, int bm, int bn)
{
    const int tid  = threadIdx.x;
    const int wid  = tid >> 5;
    const int lane = tid & 31;
    const int wm   = wid >> 2;
    const int wn   = wid & 3;

    const int lrow  = tid >> 1;
    const int lsegB = (tid & 1) * 32;
    const uint32_t so = (uint32_t)lrow * ROWB + (uint32_t)lsegB;
    const bf16* pAh = Ah + (size_t)(bm + lrow) * K + lsegB / 2;
    const bf16* pAl = Al + (size_t)(bm + lrow) * K + lsegB / 2;
    const bf16* pBh = Bh + (size_t)(bn + lrow) * K + lsegB / 2;
    const bf16* pBl = Bl + (size_t)(bn + lrow) * K + lsegB / 2;

    const uint32_t sb = smem_u32(dsm);
    const uint32_t laneOff = (uint32_t)(lane & 15) * ROWB + (uint32_t)(lane >> 4) * 16;

    float acc[4][4][4] = {};

    {
        const uint32_t s0 = sb;
        CPA16(s0 + 0 * TILEB + so,      pAh);
        CPA16(s0 + 0 * TILEB + so + 16, pAh + 8);
        CPA16(s0 + 1 * TILEB + so,      pAl);
        CPA16(s0 + 1 * TILEB + so + 16, pAl + 8);
        CPA16(s0 + 2 * TILEB + so,      pBh);
        CPA16(s0 + 2 * TILEB + so + 16, pBh + 8);
        CPA16(s0 + 3 * TILEB + so,      pBl);
        CPA16(s0 + 3 * TILEB + so + 16, pBl + 8);
        CPA_COMMIT();
    }

    const int NC = K >> 5;
    for (int c = 0; c < NC; c++) {
        CPA_WAIT0();
        __syncthreads();

        if (c + 1 < NC) {
            const int k1 = (c + 1) << 5;
            const uint32_t s1 = sb + (uint32_t)((c + 1) & 1) * STAGE;
            CPA16(s1 + 0 * TILEB + so,      pAh + k1);
            CPA16(s1 + 0 * TILEB + so + 16, pAh + k1 + 8);
            CPA16(s1 + 1 * TILEB + so,      pAl + k1);
            CPA16(s1 + 1 * TILEB + so + 16, pAl + k1 + 8);
            CPA16(s1 + 2 * TILEB + so,      pBh + k1);
            CPA16(s1 + 2 * TILEB + so + 16, pBh + k1 + 8);
            CPA16(s1 + 3 * TILEB + so,      pBl + k1);
            CPA16(s1 + 3 * TILEB + so + 16, pBl + k1 + 8);
            CPA_COMMIT();
        }

        const uint32_t sbase = sb + (uint32_t)(c & 1) * STAGE;
        const uint32_t aH = sbase + 0 * TILEB + (uint32_t)wm * 64 * ROWB + laneOff;
        const uint32_t aL = aH + TILEB;
        const uint32_t bH = sbase + 2 * TILEB + (uint32_t)wn * 32 * ROWB + laneOff;
        const uint32_t bL = bH + TILEB;

        #pragma unroll
        for (int ks = 0; ks < 2; ks++) {
            const uint32_t ko = ks * 32;
            uint32_t a[4][4], bh[2][4], bl[2][4];
            LDSM4(bh[0], bH + ko);
            LDSM4(bh[1], bH + 16 * ROWB + ko);
            LDSM4(bl[0], bL + ko);
            LDSM4(bl[1], bL + 16 * ROWB + ko);
            #pragma unroll
            for (int mt = 0; mt < 4; mt++) LDSM4(a[mt], aH + mt * 16 * ROWB + ko);

            #pragma unroll
            for (int mt = 0; mt < 4; mt++)
                #pragma unroll
                for (int nt = 0; nt < 4; nt++)
                    MMA(acc[mt][nt], a[mt], bh[nt >> 1][nt & 1], bh[nt >> 1][(nt & 1) + 2]);
            #pragma unroll
            for (int mt = 0; mt < 4; mt++)
                #pragma unroll
                for (int nt = 0; nt < 4; nt++)
                    MMA(acc[mt][nt], a[mt], bl[nt >> 1][nt & 1], bl[nt >> 1][(nt & 1) + 2]);

            #pragma unroll
            for (int mt = 0; mt < 4; mt++) LDSM4(a[mt], aL + mt * 16 * ROWB + ko);
            #pragma unroll
            for (int mt = 0; mt < 4; mt++)
                #pragma unroll
                for (int nt = 0; nt < 4; nt++)
                    MMA(acc[mt][nt], a[mt], bh[nt >> 1][nt & 1], bh[nt >> 1][(nt & 1) + 2]);
        }
    }

    const int lr = lane >> 2;
    const int lc = (lane & 3) * 2;
    #pragma unroll
    for (int mt = 0; mt < 4; mt++) {
        const int m0 = bm + wm * 64 + mt * 16 + lr;
        #pragma unroll
        for (int nt = 0; nt < 4; nt++) {
            const int n0 = bn + wn * 32 + nt * 8 + lc;
            float bx = 0.f, by = 0.f;
            if (bias) { bx = bias[n0]; by = bias[n0 + 1]; }
            float v00 = acc[mt][nt][0] + bx, v01 = acc[mt][nt][1] + by;
            float v10 = acc[mt][nt][2] + bx, v11 = acc[mt][nt][3] + by;
            if (Cf) {
                *(float2*)(Cf + (size_t)m0 * N + n0)       = make_float2(v00, v01);
                *(float2*)(Cf + (size_t)(m0 + 8) * N + n0) = make_float2(v10, v11);
            } else {
                bf16 h0, h1, l0, l1;
                split1(v00, h0, l0); split1(v01, h1, l1);
                *(uint32_t*)(Ch + (size_t)m0 * N + n0) = pk(h0, h1);
                *(uint32_t*)(Cl + (size_t)m0 * N + n0) = pk(l0, l1);
                split1(v10, h0, l0); split1(v11, h1, l1);
                *(uint32_t*)(Ch + (size_t)(m0 + 8) * N + n0) = pk(h0, h1);
                *(uint32_t*)(Cl + (size_t)(m0 + 8) * N + n0) = pk(l0, l1);
            }
        }
    }
}

// QK^T GEMM -> fp32 scores (pointers pre-offset per batch; z unused).
__global__ __launch_bounds__(256, 2)
void gemm_sp(const bf16* __restrict__ Ah, const bf16* __restrict__ Al,
             const bf16* __restrict__ Bh, const bf16* __restrict__ Bl,
             float* __restrict__ Cf,
             int M, int N, int K, size_t sA, size_t sB, size_t sC)
{
    const size_t zA = (size_t)blockIdx.z * sA;
    const size_t zB = (size_t)blockIdx.z * sB;
    const size_t zC = (size_t)blockIdx.z * sC;
    gemm_body(Ah + zA, Al + zA, Bh + zB, Bl + zB, nullptr,
              Cf + zC, nullptr, nullptr,
              M, N, K, blockIdx.y * 128, blockIdx.x * 128);
}

// Fused Q/K projection: z selects {Q, K} (split bf16 outputs).
__global__ __launch_bounds__(256, 2)
void gemm_qkv(const bf16* __restrict__ xh, const bf16* __restrict__ xl,
              const bf16* __restrict__ Wqh, const bf16* __restrict__ Wql,
              const bf16* __restrict__ Wkh, const bf16* __restrict__ Wkl,
              const float* __restrict__ bq, const float* __restrict__ bk,
              bf16* __restrict__ Qh, bf16* __restrict__ Ql,
              bf16* __restrict__ Kh, bf16* __restrict__ Kl)
{
    const bf16 *Bh, *Bl; const float* bias; bf16 *Ch, *Cl;
    if (blockIdx.z == 0) { Bh = Wqh; Bl = Wql; bias = bq; Ch = Qh; Cl = Ql; }
    else                 { Bh = Wkh; Bl = Wkl; bias = bk; Ch = Kh; Cl = Kl; }
    gemm_body(xh, xl, Bh, Bl, bias, nullptr, Ch, Cl,
              BATCH * SEQ, DIM, DIM, blockIdx.y * 128, blockIdx.x * 128);
}

// ---------------------------------------------------------------------------
// Single-term fp16 NT GEMM: C[M,N] = scale * (A[M,K] * B[N,K]^T) (+ bias).
// ---------------------------------------------------------------------------
__global__ __launch_bounds__(256, 2)
void gemm_h16(const __half* __restrict__ A, const __half* __restrict__ B,
              const float* __restrict__ bias,
              float* __restrict__ Cf, __half* __restrict__ C16, float scale,
              int M, int N, int K, size_t sA, size_t sB, size_t sC)
{
    const __half* Az = A + (size_t)blockIdx.z * sA;
    const __half* Bz = B + (size_t)blockIdx.z * sB;
    const size_t  zC = (size_t)blockIdx.z * sC;

    const int tid  = threadIdx.x;
    const int wid  = tid >> 5;
    const int lane = tid & 31;
    const int wm   = wid >> 2;
    const int wn   = wid & 3;
    const int bm = blockIdx.y * 128;
    const int bn = blockIdx.x * 128;

    const int lrow  = tid >> 1;
    const int lsegB = (tid & 1) * 32;
    const uint32_t so = (uint32_t)lrow * ROWB + (uint32_t)lsegB;
    const __half* pA = Az + (size_t)(bm + lrow) * K + lsegB / 2;
    const __half* pB = Bz + (size_t)(bn + lrow) * K + lsegB / 2;

    const uint32_t sb = smem_u32(dsm);
    const uint32_t laneOff = (uint32_t)(lane & 15) * ROWB + (uint32_t)(lane >> 4) * 16;

    float acc[4][4][4] = {};

    {
        CPA16(sb + so,              pA);
        CPA16(sb + so + 16,         pA + 8);
        CPA16(sb + TILEB + so,      pB);
        CPA16(sb + TILEB + so + 16, pB + 8);
        CPA_COMMIT();
    }

    const int NC = K >> 5;
    for (int c = 0; c < NC; c++) {
        CPA_WAIT0();
        __syncthreads();

        if (c + 1 < NC) {
            const int k1 = (c + 1) << 5;
            const uint32_t s1 = sb + (uint32_t)((c + 1) & 1) * STAV;
            CPA16(s1 + so,              pA + k1);
            CPA16(s1 + so + 16,         pA + k1 + 8);
            CPA16(s1 + TILEB + so,      pB + k1);
            CPA16(s1 + TILEB + so + 16, pB + k1 + 8);
            CPA_COMMIT();
        }

        const uint32_t sbase = sb + (uint32_t)(c & 1) * STAV;
        const uint32_t aB = sbase + (uint32_t)wm * 64 * ROWB + laneOff;
        const uint32_t bB = sbase + TILEB + (uint32_t)wn * 32 * ROWB + laneOff;

        #pragma unroll
        for (int ks = 0; ks < 2; ks++) {
            const uint32_t ko = ks * 32;
            uint32_t a[4][4], b[2][4];
            LDSM4(b[0], bB + ko);
            LDSM4(b[1], bB + 16 * ROWB + ko);
            #pragma unroll
            for (int mt = 0; mt < 4; mt++) LDSM4(a[mt], aB + mt * 16 * ROWB + ko);
            #pragma unroll
            for (int mt = 0; mt < 4; mt++)
                #pragma unroll
                for (int nt = 0; nt < 4; nt++)
                    MMA_F16(acc[mt][nt], a[mt], b[nt >> 1][nt & 1], b[nt >> 1][(nt & 1) + 2]);
        }
    }

    const int lr = lane >> 2;
    const int lc = (lane & 3) * 2;
    #pragma unroll
    for (int mt = 0; mt < 4; mt++) {
        const int m0 = bm + wm * 64 + mt * 16 + lr;
        #pragma unroll
        for (int nt = 0; nt < 4; nt++) {
            const int n0 = bn + wn * 32 + nt * 8 + lc;
            float bx = 0.f, by = 0.f;
            if (bias) { bx = bias[n0]; by = bias[n0 + 1]; }
            float v00 = acc[mt][nt][0] * scale + bx, v01 = acc[mt][nt][1] * scale + by;
            float v10 = acc[mt][nt][2] * scale + bx, v11 = acc[mt][nt][3] * scale + by;
            if (Cf) {
                *(float2*)(Cf + zC + (size_t)m0 * N + n0)       = make_float2(v00, v01);
                *(float2*)(Cf + zC + (size_t)(m0 + 8) * N + n0) = make_float2(v10, v11);
            } else {
                *(uint32_t*)(C16 + zC + (size_t)m0 * N + n0)       = pkh(v00, v01);
                *(uint32_t*)(C16 + zC + (size_t)(m0 + 8) * N + n0) = pkh(v10, v11);
            }
        }
    }
}

// ---------------------------------------------------------------------------
// Merged fp32 conversions: z selects {x -> (xh,xl,xf), Wq, Wk, Wv -> Wvf}.
// ---------------------------------------------------------------------------
__global__ __launch_bounds__(256)
void split_all(const float* __restrict__ x,  const float* __restrict__ Wq,
               const float* __restrict__ Wk, const float* __restrict__ Wv,
               bf16* __restrict__ xh,  bf16* __restrict__ xl, __half* __restrict__ xf,
               bf16* __restrict__ Wqh, bf16* __restrict__ Wql,
               bf16* __restrict__ Wkh, bf16* __restrict__ Wkl,
               __half* __restrict__ Wvf)
{
    const int z = blockIdx.z;
    if (z == 3) {
        for (size_t i = (size_t)blockIdx.x * blockDim.x + threadIdx.x; i < NW / 4;
             i += (size_t)gridDim.x * blockDim.x) {
            float4 v = ((const float4*)Wv)[i];
            ((uint2*)Wvf)[i] = make_uint2(pkh(v.x, v.y), pkh(v.z, v.w));
        }
        return;
    }
    const float* in; bf16 *hi, *lo; size_t n4;
    if (z == 0)      { in = x;  hi = xh;  lo = xl;  n4 = NX / 4; }
    else if (z == 1) { in = Wq; hi = Wqh; lo = Wql; n4 = NW / 4; }
    else             { in = Wk; hi = Wkh; lo = Wkl; n4 = NW / 4; }
    for (size_t i = (size_t)blockIdx.x * blockDim.x + threadIdx.x; i < n4;
         i += (size_t)gridDim.x * blockDim.x) {
        float4 v = ((const float4*)in)[i];
        bf16 h0, h1, h2, h3, l0, l1, l2, l3;
        split1(v.x, h0, l0); split1(v.y, h1, l1);
        split1(v.z, h2, l2); split1(v.w, h3, l3);
        ((uint2*)hi)[i] = make_uint2(pk(h0, h1), pk(h2, h3));
        ((uint2*)lo)[i] = make_uint2(pk(l0, l1), pk(l2, l3));
        if (z == 0)
            ((uint2*)xf)[i] = make_uint2(pkh(v.x, v.y), pkh(v.z, v.w));
    }
}

// ---------------------------------------------------------------------------
// fp16 transpose (z = batch): Vt[b][d][s] = V[b][s][d]
// ---------------------------------------------------------------------------
__global__ __launch_bounds__(256)
void transpose_vf(const __half* __restrict__ V, __half* __restrict__ Vt)
{
    __shared__ __half t[32][33];
    const int b  = blockIdx.z;
    const __half* src = V  + (size_t)b * SEQ * DIM;
    __half*       dst = Vt + (size_t)b * SEQ * DIM;
    const int d0 = blockIdx.x * 32;
    const int s0 = blockIdx.y * 32;
    const int tx = threadIdx.x;
    const int ty = threadIdx.y;
    #pragma unroll
    for (int j = 0; j < 32; j += 8)
        t[ty + j][tx] = src[(size_t)(s0 + ty + j) * DIM + d0 + tx];
    __syncthreads();
    #pragma unroll
    for (int j = 0; j < 32; j += 8)
        dst[(size_t)(d0 + ty + j) * SEQ + s0 + tx] = t[tx][ty + j];
}

// ---------------------------------------------------------------------------
// Row softmax over SEQ=2048 -> fp16 probabilities (UNscaled; NORM folded into AV).
// ---------------------------------------------------------------------------
__global__ __launch_bounds__(256)
void softmax_f16(const float* __restrict__ S, __half* __restrict__ Pf)
{
    const float* row = S + (size_t)blockIdx.x * SEQ;
    const int tid = threadIdx.x;

    float4 v0 = *(const float4*)(row + tid * 4);
    float4 v1 = *(const float4*)(row + 1024 + tid * 4);

    float m = fmaxf(fmaxf(fmaxf(v0.x, v0.y), fmaxf(v0.z, v0.w)),
                    fmaxf(fmaxf(v1.x, v1.y), fmaxf(v1.z, v1.w)));
    #pragma unroll
    for (int o = 16; o > 0; o >>= 1)
        m = fmaxf(m, __shfl_xor_sync(0xffffffffu, m, o));

    __shared__ float red[8];
    const int wid = tid >> 5, lane = tid & 31;
    if (lane == 0) red[wid] = m;
    __syncthreads();
    m = red[0];
    #pragma unroll
    for (int w = 1; w < 8; w++) m = fmaxf(m, red[w]);

    v0.x = __expf(v0.x - m); v0.y = __expf(v0.y - m);
    v0.z = __expf(v0.z - m); v0.w = __expf(v0.w - m);
    v1.x = __expf(v1.x - m); v1.y = __expf(v1.y - m);
    v1.z = __expf(v1.z - m); v1.w = __expf(v1.w - m);

    float s = (v0.x + v0.y) + (v0.z + v0.w) + (v1.x + v1.y) + (v1.z + v1.w);
    #pragma unroll
    for (int o = 16; o > 0; o >>= 1)
        s += __shfl_xor_sync(0xffffffffu, s, o);

    __shared__ float red2[8];
    if (lane == 0) red2[wid] = s;
    __syncthreads();
    s = red2[0];
    #pragma unroll
    for (int w = 1; w < 8; w++) s += red2[w];

    const float scale = 1.0f / s;      // NORM_FACT applied in AV epilogue
    v0.x *= scale; v0.y *= scale; v0.z *= scale; v0.w *= scale;
    v1.x *= scale; v1.y *= scale; v1.z *= scale; v1.w *= scale;

    __half* ph = Pf + (size_t)blockIdx.x * SEQ;
    *(uint2*)(ph + tid * 4)        = make_uint2(pkh(v0.x, v0.y), pkh(v0.z, v0.w));
    *(uint2*)(ph + 1024 + tid * 4) = make_uint2(pkh(v1.x, v1.y), pkh(v1.z, v1.w));
}

// ---------------------------------------------------------------------------
extern "C" void kernel_launch(void* const* d_in, const int* in_sizes, int n_in,
                              void* d_out, int out_size)
{
    const float* x  = (const float*)d_in[0];
    const float* Wq = (const float*)d_in[1];
    const float* bq = (const float*)d_in[2];
    const float* Wk = (const float*)d_in[3];
    const float* bk = (const float*)d_in[4];
    const float* Wv = (const float*)d_in[5];
    const float* bv = (const float*)d_in[6];
    float* out = (float*)d_out;

    bf16 *xh, *xl, *Wqh, *Wql, *Wkh, *Wkl;
    bf16 *Qh, *Ql, *Kh, *Kl;
    __half *xf, *Wvf, *Vf, *Vtf, *Pf;
    float* P;
    cudaGetSymbolAddress((void**)&xh,  g_xh);  cudaGetSymbolAddress((void**)&xl,  g_xl);
    cudaGetSymbolAddress((void**)&Wqh, g_Wqh); cudaGetSymbolAddress((void**)&Wql, g_Wql);
    cudaGetSymbolAddress((void**)&Wkh, g_Wkh); cudaGetSymbolAddress((void**)&Wkl, g_Wkl);
    cudaGetSymbolAddress((void**)&Qh,  g_Qh);  cudaGetSymbolAddress((void**)&Ql,  g_Ql);
    cudaGetSymbolAddress((void**)&Kh,  g_Kh);  cudaGetSymbolAddress((void**)&Kl,  g_Kl);
    cudaGetSymbolAddress((void**)&xf,  g_xf);
    cudaGetSymbolAddress((void**)&Wvf, g_Wvf);
    cudaGetSymbolAddress((void**)&Vf,  g_Vf);
    cudaGetSymbolAddress((void**)&Vtf, g_Vtf);
    cudaGetSymbolAddress((void**)&Pf,  g_Pf);
    cudaGetSymbolAddress((void**)&P,   g_P);

    cudaFuncSetAttribute(gemm_sp,  cudaFuncAttributeMaxDynamicSharedMemorySize, SMEM_TOTAL);
    cudaFuncSetAttribute(gemm_qkv, cudaFuncAttributeMaxDynamicSharedMemorySize, SMEM_TOTAL);
    cudaFuncSetAttribute(gemm_h16, cudaFuncAttributeMaxDynamicSharedMemorySize, SMEM_AV);

    // One-time side streams + events (host resources, no device memory).
    static cudaStream_t s1 = nullptr, s2 = nullptr;
    static cudaEvent_t eFork = nullptr, eJoin = nullptr, eEnd = nullptr;
    static cudaEvent_t eQK[BATCH] = {};
    if (!s1) {
        cudaStreamCreateWithFlags(&s1, cudaStreamNonBlocking);
        cudaStreamCreateWithFlags(&s2, cudaStreamNonBlocking);
        cudaEventCreateWithFlags(&eFork, cudaEventDisableTiming);
        cudaEventCreateWithFlags(&eJoin, cudaEventDisableTiming);
        cudaEventCreateWithFlags(&eEnd,  cudaEventDisableTiming);
        for (int b = 0; b < BATCH; b++)
            cudaEventCreateWithFlags(&eQK[b], cudaEventDisableTiming);
    }

    const size_t sQK = (size_t)SEQ * DIM;   // per-batch Q/K stride
    const size_t sP  = (size_t)SEQ * SEQ;   // per-batch score stride

    // 0) conversions
    {
        dim3 grid(1024, 1, 4);
        split_all<<<grid, 256>>>(x, Wq, Wk, Wv, xh, xl, xf,
                                 Wqh, Wql, Wkh, Wkl, Wvf);
    }

    // Fork: V pipeline on s1 (independent of Q/K chain).
    cudaEventRecord(eFork, 0);
    cudaStreamWaitEvent(s1, eFork, 0);
    cudaStreamWaitEvent(s2, eFork, 0);

    // 1a) Q/K projections (main stream)
    {
        dim3 grid(DIM / 128, (BATCH * SEQ) / 128, 2);
        gemm_qkv<<<grid, 256, SMEM_TOTAL>>>(xh, xl, Wqh, Wql, Wkh, Wkl,
                                            bq, bk, Qh, Ql, Kh, Kl);
    }

    // 1b) V projection + transpose on s1 (hidden under Q/K proj + QK)
    {
        dim3 grid(DIM / 128, (BATCH * SEQ) / 128, 1);
        gemm_h16<<<grid, 256, SMEM_AV, s1>>>(xf, Wvf, bv, nullptr, Vf, 1.0f,
                                             BATCH * SEQ, DIM, DIM, 0, 0, 0);
        dim3 tgrid(DIM / 32, SEQ / 32, BATCH);
        transpose_vf<<<tgrid, dim3(32, 8), 0, s1>>>(Vf, Vtf);
        cudaEventRecord(eJoin, s1);
    }
    cudaStreamWaitEvent(s2, eJoin, 0);   // s2's AV launches need Vtf

    // 2) Per-batch pipeline: QK(b) on main; softmax(b)+AV(b) on s2 overlap QK(b+1).
    for (int b = 0; b < BATCH; b++) {
        dim3 grid(SEQ / 128, SEQ / 128, 1);
        gemm_sp<<<grid, 256, SMEM_TOTAL>>>(Qh + b * sQK, Ql + b * sQK,
                                           Kh + b * sQK, Kl + b * sQK,
                                           P + b * sP,
                                           SEQ, SEQ, DIM, 0, 0, 0);
        cudaEventRecord(eQK[b], 0);
        cudaStreamWaitEvent(s2, eQK[b], 0);

        softmax_f16<<<SEQ, 256, 0, s2>>>(P + b * sP, Pf + b * sP);

        dim3 agrid(DIM / 128, SEQ / 128, 1);
        gemm_h16<<<agrid, 256, SMEM_AV, s2>>>(Pf + b * sP, Vtf + b * sQK, nullptr,
                                              out + b * sQK, nullptr, NORM_FACT,
                                              SEQ, DIM, SEQ, 0, 0, 0);
    }

    // Join: main stream completes only after all s2 work.
    cudaEventRecord(eEnd, s2);
    cudaStreamWaitEvent(0, eEnd, 0);
}

// round 14
// speedup vs baseline: 1.0063x; 1.0063x over previous
#include <cuda_runtime.h>
#include <cuda_bf16.h>
#include <cuda_fp16.h>
#include <cstdint>

#define BATCH 4
#define SEQ   2048
#define DIM   1024
#define NORM_FACT 0.03125f   // 1/sqrt(1024), applied POST-softmax per reference

typedef __nv_bfloat16 bf16;

// ---------------------------------------------------------------------------
// Scratch (allocation-free rule: __device__ globals).
// Q/K pre-split bf16 hi/lo (3-term path); x/Wv/V/P fp16 (1-term paths).
// ---------------------------------------------------------------------------
#define NX  ((size_t)BATCH * SEQ * DIM)   // 8M
#define NW  ((size_t)DIM * DIM)           // 1M
#define NP  ((size_t)BATCH * SEQ * SEQ)   // 16M

__device__ __align__(256) bf16 g_xh[NX],  g_xl[NX];
__device__ __align__(256) bf16 g_Wqh[NW], g_Wql[NW];
__device__ __align__(256) bf16 g_Wkh[NW], g_Wkl[NW];
__device__ __align__(256) bf16 g_Qh[NX],  g_Ql[NX];
__device__ __align__(256) bf16 g_Kh[NX],  g_Kl[NX];
__device__ __align__(256) __half g_xf[NX];
__device__ __align__(256) __half g_Wvf[NW];
__device__ __align__(256) __half g_Vf[NX];
__device__ __align__(256) __half g_Vtf[NX];
__device__ __align__(256) __half g_Pf[NP];
__device__ __align__(256) float  g_P[NP];

// ---------------------------------------------------------------------------
// Smem layouts. Row stride 80 B -> ldmatrix conflict-free, cp.async 16B-aligned.
// ---------------------------------------------------------------------------
#define ROWB   80
#define TILEB  (128 * ROWB)          // 10240
#define STAGE  (4 * TILEB)           // 40960
#define SMEM_TOTAL (2 * STAGE)       // 81920
#define STAV   (2 * TILEB)           // 20480
#define SMEM_AV (2 * STAV)           // 40960

extern __shared__ char dsm[];

__device__ __forceinline__ uint32_t smem_u32(const void* p) {
    uint32_t a;
    asm("{ .reg .u64 t; cvta.to.shared.u64 t, %1; cvt.u32.u64 %0, t; }"
        : "=r"(a) : "l"(p));
    return a;
}

#define CPA16(dst, src) \
    asm volatile("cp.async.cg.shared.global [%0], [%1], 16;" :: "r"(dst), "l"(src))
#define CPA_COMMIT() asm volatile("cp.async.commit_group;" ::: "memory")
#define CPA_WAIT0()  asm volatile("cp.async.wait_group 0;" ::: "memory")

#define LDSM4(R, addr)                                                        \
    asm volatile("ldmatrix.sync.aligned.m8n8.x4.shared.b16 {%0,%1,%2,%3}, [%4];" \
                 : "=r"((R)[0]), "=r"((R)[1]), "=r"((R)[2]), "=r"((R)[3])     \
                 : "r"(addr))

#define MMA(cc, A, b0, b1)                                                    \
    asm volatile("mma.sync.aligned.m16n8k16.row.col.f32.bf16.bf16.f32 "       \
                 "{%0,%1,%2,%3},{%4,%5,%6,%7},{%8,%9},{%0,%1,%2,%3};"         \
                 : "+f"((cc)[0]), "+f"((cc)[1]), "+f"((cc)[2]), "+f"((cc)[3]) \
                 : "r"((A)[0]), "r"((A)[1]), "r"((A)[2]), "r"((A)[3]),        \
                   "r"(b0), "r"(b1))

#define MMA_F16(cc, A, b0, b1)                                                \
    asm volatile("mma.sync.aligned.m16n8k16.row.col.f32.f16.f16.f32 "         \
                 "{%0,%1,%2,%3},{%4,%5,%6,%7},{%8,%9},{%0,%1,%2,%3};"         \
                 : "+f"((cc)[0]), "+f"((cc)[1]), "+f"((cc)[2]), "+f"((cc)[3]) \
                 : "r"((A)[0]), "r"((A)[1]), "r"((A)[2]), "r"((A)[3]),        \
                   "r"(b0), "r"(b1))

__device__ __forceinline__ uint32_t pk(bf16 a, bf16 b) {
    return (uint32_t)__bfloat16_as_ushort(a) | ((uint32_t)__bfloat16_as_ushort(b) << 16);
}

__device__ __forceinline__ uint32_t pkh(float a, float b) {
    __half2 h = __floats2half2_rn(a, b);
    return *(uint32_t*)&h;
}

__device__ __forceinline__ void split1(float v, bf16& h, bf16& l) {
    h = __float2bfloat16_rn(v);
    l = __float2bfloat16_rn(v - __bfloat162float(h));
}

// ---------------------------------------------------------------------------
// 3-term split-precision NT GEMM body (validated R7 structure).
// ---------------------------------------------------------------------------
__device__ __forceinline__
void gemm_body(const bf16* __restrict__ Ah, const bf16* __restrict__ Al,
               const bf16* __restrict__ Bh, const bf16* __restrict__ Bl,
               const float* __restrict__ bias,
               float* __restrict__ Cf, bf16* __restrict__ Ch, bf16* __restrict__ Cl,
               int M, int N, int K, int bm, int bn)
{
    const int tid  = threadIdx.x;
    const int wid  = tid >> 5;
    const int lane = tid & 31;
    const int wm   = wid >> 2;
    const int wn   = wid & 3;

    const int lrow  = tid >> 1;
    const int lsegB = (tid & 1) * 32;
    const uint32_t so = (uint32_t)lrow * ROWB + (uint32_t)lsegB;
    const bf16* pAh = Ah + (size_t)(bm + lrow) * K + lsegB / 2;
    const bf16* pAl = Al + (size_t)(bm + lrow) * K + lsegB / 2;
    const bf16* pBh = Bh + (size_t)(bn + lrow) * K + lsegB / 2;
    const bf16* pBl = Bl + (size_t)(bn + lrow) * K + lsegB / 2;

    const uint32_t sb = smem_u32(dsm);
    const uint32_t laneOff = (uint32_t)(lane & 15) * ROWB + (uint32_t)(lane >> 4) * 16;

    float acc[4][4][4] = {};

    {
        const uint32_t s0 = sb;
        CPA16(s0 + 0 * TILEB + so,      pAh);
        CPA16(s0 + 0 * TILEB + so + 16, pAh + 8);
        CPA16(s0 + 1 * TILEB + so,      pAl);
        CPA16(s0 + 1 * TILEB + so + 16, pAl + 8);
        CPA16(s0 + 2 * TILEB + so,      pBh);
        CPA16(s0 + 2 * TILEB + so + 16, pBh + 8);
        CPA16(s0 + 3 * TILEB + so,      pBl);
        CPA16(s0 + 3 * TILEB + so + 16, pBl + 8);
        CPA_COMMIT();
    }

    const int NC = K >> 5;
    for (int c = 0; c < NC; c++) {
        CPA_WAIT0();
        __syncthreads();

        if (c + 1 < NC) {
            const int k1 = (c + 1) << 5;
            const uint32_t s1 = sb + (uint32_t)((c + 1) & 1) * STAGE;
            CPA16(s1 + 0 * TILEB + so,      pAh + k1);
            CPA16(s1 + 0 * TILEB + so + 16, pAh + k1 + 8);
            CPA16(s1 + 1 * TILEB + so,      pAl + k1);
            CPA16(s1 + 1 * TILEB + so + 16, pAl + k1 + 8);
            CPA16(s1 + 2 * TILEB + so,      pBh + k1);
            CPA16(s1 + 2 * TILEB + so + 16, pBh + k1 + 8);
            CPA16(s1 + 3 * TILEB + so,      pBl + k1);
            CPA16(s1 + 3 * TILEB + so + 16, pBl + k1 + 8);
            CPA_COMMIT();
        }

        const uint32_t sbase = sb + (uint32_t)(c & 1) * STAGE;
        const uint32_t aH = sbase + 0 * TILEB + (uint32_t)wm * 64 * ROWB + laneOff;
        const uint32_t aL = aH + TILEB;
        const uint32_t bH = sbase + 2 * TILEB + (uint32_t)wn * 32 * ROWB + laneOff;
        const uint32_t bL = bH + TILEB;

        #pragma unroll
        for (int ks = 0; ks < 2; ks++) {
            const uint32_t ko = ks * 32;
            uint32_t a[4][4], bh[2][4], bl[2][4];
            LDSM4(bh[0], bH + ko);
            LDSM4(bh[1], bH + 16 * ROWB + ko);
            LDSM4(bl[0], bL + ko);
            LDSM4(bl[1], bL + 16 * ROWB + ko);
            #pragma unroll
            for (int mt = 0; mt < 4; mt++) LDSM4(a[mt], aH + mt * 16 * ROWB + ko);

            #pragma unroll
            for (int mt = 0; mt < 4; mt++)
                #pragma unroll
                for (int nt = 0; nt < 4; nt++)
                    MMA(acc[mt][nt], a[mt], bh[nt >> 1][nt & 1], bh[nt >> 1][(nt & 1) + 2]);
            #pragma unroll
            for (int mt = 0; mt < 4; mt++)
                #pragma unroll
                for (int nt = 0; nt < 4; nt++)
                    MMA(acc[mt][nt], a[mt], bl[nt >> 1][nt & 1], bl[nt >> 1][(nt & 1) + 2]);

            #pragma unroll
            for (int mt = 0; mt < 4; mt++) LDSM4(a[mt], aL + mt * 16 * ROWB + ko);
            #pragma unroll
            for (int mt = 0; mt < 4; mt++)
                #pragma unroll
                for (int nt = 0; nt < 4; nt++)
                    MMA(acc[mt][nt], a[mt], bh[nt >> 1][nt & 1], bh[nt >> 1][(nt & 1) + 2]);
        }
    }

    const int lr = lane >> 2;
    const int lc = (lane & 3) * 2;
    #pragma unroll
    for (int mt = 0; mt < 4; mt++) {
        const int m0 = bm + wm * 64 + mt * 16 + lr;
        #pragma unroll
        for (int nt = 0; nt < 4; nt++) {
            const int n0 = bn + wn * 32 + nt * 8 + lc;
            float bx = 0.f, by = 0.f;
            if (bias) { bx = bias[n0]; by = bias[n0 + 1]; }
            float v00 = acc[mt][nt][0] + bx, v01 = acc[mt][nt][1] + by;
            float v10 = acc[mt][nt][2] + bx, v11 = acc[mt][nt][3] + by;
            if (Cf) {
                *(float2*)(Cf + (size_t)m0 * N + n0)       = make_float2(v00, v01);
                *(float2*)(Cf + (size_t)(m0 + 8) * N + n0) = make_float2(v10, v11);
            } else {
                bf16 h0, h1, l0, l1;
                split1(v00, h0, l0); split1(v01, h1, l1);
                *(uint32_t*)(Ch + (size_t)m0 * N + n0) = pk(h0, h1);
                *(uint32_t*)(Cl + (size_t)m0 * N + n0) = pk(l0, l1);
                split1(v10, h0, l0); split1(v11, h1, l1);
                *(uint32_t*)(Ch + (size_t)(m0 + 8) * N + n0) = pk(h0, h1);
                *(uint32_t*)(Cl + (size_t)(m0 + 8) * N + n0) = pk(l0, l1);
            }
        }
    }
}

// Batched QK^T GEMM -> fp32 scores.
__global__ __launch_bounds__(256, 2)
void gemm_sp(const bf16* __restrict__ Ah, const bf16* __restrict__ Al,
             const bf16* __restrict__ Bh, const bf16* __restrict__ Bl,
             float* __restrict__ Cf,
             int M, int N, int K, size_t sA, size_t sB, size_t sC)
{
    const size_t zA = (size_t)blockIdx.z * sA;
    const size_t zB = (size_t)blockIdx.z * sB;
    const size_t zC = (size_t)blockIdx.z * sC;
    gemm_body(Ah + zA, Al + zA, Bh + zB, Bl + zB, nullptr,
              Cf + zC, nullptr, nullptr,
              M, N, K, blockIdx.y * 128, blockIdx.x * 128);
}

// Fused Q/K projection: z selects {Q, K} (split bf16 outputs).
__global__ __launch_bounds__(256, 2)
void gemm_qkv(const bf16* __restrict__ xh, const bf16* __restrict__ xl,
              const bf16* __restrict__ Wqh, const bf16* __restrict__ Wql,
              const bf16* __restrict__ Wkh, const bf16* __restrict__ Wkl,
              const float* __restrict__ bq, const float* __restrict__ bk,
              bf16* __restrict__ Qh, bf16* __restrict__ Ql,
              bf16* __restrict__ Kh, bf16* __restrict__ Kl)
{
    const bf16 *Bh, *Bl; const float* bias; bf16 *Ch, *Cl;
    if (blockIdx.z == 0) { Bh = Wqh; Bl = Wql; bias = bq; Ch = Qh; Cl = Ql; }
    else                 { Bh = Wkh; Bl = Wkl; bias = bk; Ch = Kh; Cl = Kl; }
    gemm_body(xh, xl, Bh, Bl, bias, nullptr, Ch, Cl,
              BATCH * SEQ, DIM, DIM, blockIdx.y * 128, blockIdx.x * 128);
}

// ---------------------------------------------------------------------------
// Single-term fp16 NT GEMM: C[M,N] = scale * (A[M,K] * B[N,K]^T) (+ bias).
// ---------------------------------------------------------------------------
__global__ __launch_bounds__(256, 2)
void gemm_h16(const __half* __restrict__ A, const __half* __restrict__ B,
              const float* __restrict__ bias,
              float* __restrict__ Cf, __half* __restrict__ C16, float scale,
              int M, int N, int K, size_t sA, size_t sB, size_t sC)
{
    const __half* Az = A + (size_t)blockIdx.z * sA;
    const __half* Bz = B + (size_t)blockIdx.z * sB;
    const size_t  zC = (size_t)blockIdx.z * sC;

    const int tid  = threadIdx.x;
    const int wid  = tid >> 5;
    const int lane = tid & 31;
    const int wm   = wid >> 2;
    const int wn   = wid & 3;
    const int bm = blockIdx.y * 128;
    const int bn = blockIdx.x * 128;

    const int lrow  = tid >> 1;
    const int lsegB = (tid & 1) * 32;
    const uint32_t so = (uint32_t)lrow * ROWB + (uint32_t)lsegB;
    const __half* pA = Az + (size_t)(bm + lrow) * K + lsegB / 2;
    const __half* pB = Bz + (size_t)(bn + lrow) * K + lsegB / 2;

    const uint32_t sb = smem_u32(dsm);
    const uint32_t laneOff = (uint32_t)(lane & 15) * ROWB + (uint32_t)(lane >> 4) * 16;

    float acc[4][4][4] = {};

    {
        CPA16(sb + so,              pA);
        CPA16(sb + so + 16,         pA + 8);
        CPA16(sb + TILEB + so,      pB);
        CPA16(sb + TILEB + so + 16, pB + 8);
        CPA_COMMIT();
    }

    const int NC = K >> 5;
    for (int c = 0; c < NC; c++) {
        CPA_WAIT0();
        __syncthreads();

        if (c + 1 < NC) {
            const int k1 = (c + 1) << 5;
            const uint32_t s1 = sb + (uint32_t)((c + 1) & 1) * STAV;
            CPA16(s1 + so,              pA + k1);
            CPA16(s1 + so + 16,         pA + k1 + 8);
            CPA16(s1 + TILEB + so,      pB + k1);
            CPA16(s1 + TILEB + so + 16, pB + k1 + 8);
            CPA_COMMIT();
        }

        const uint32_t sbase = sb + (uint32_t)(c & 1) * STAV;
        const uint32_t aB = sbase + (uint32_t)wm * 64 * ROWB + laneOff;
        const uint32_t bB = sbase + TILEB + (uint32_t)wn * 32 * ROWB + laneOff;

        #pragma unroll
        for (int ks = 0; ks < 2; ks++) {
            const uint32_t ko = ks * 32;
            uint32_t a[4][4], b[2][4];
            LDSM4(b[0], bB + ko);
            LDSM4(b[1], bB + 16 * ROWB + ko);
            #pragma unroll
            for (int mt = 0; mt < 4; mt++) LDSM4(a[mt], aB + mt * 16 * ROWB + ko);
            #pragma unroll
            for (int mt = 0; mt < 4; mt++)
                #pragma unroll
                for (int nt = 0; nt < 4; nt++)
                    MMA_F16(acc[mt][nt], a[mt], b[nt >> 1][nt & 1], b[nt >> 1][(nt & 1) + 2]);
        }
    }

    const int lr = lane >> 2;
    const int lc = (lane & 3) * 2;
    #pragma unroll
    for (int mt = 0; mt < 4; mt++) {
        const int m0 = bm + wm * 64 + mt * 16 + lr;
        #pragma unroll
        for (int nt = 0; nt < 4; nt++) {
            const int n0 = bn + wn * 32 + nt * 8 + lc;
            float bx = 0.f, by = 0.f;
            if (bias) { bx = bias[n0]; by = bias[n0 + 1]; }
            float v00 = acc[mt][nt][0] * scale + bx, v01 = acc[mt][nt][1] * scale + by;
            float v10 = acc[mt][nt][2] * scale + bx, v11 = acc[mt][nt][3] * scale + by;
            if (Cf) {
                *(float2*)(Cf + zC + (size_t)m0 * N + n0)       = make_float2(v00, v01);
                *(float2*)(Cf + zC + (size_t)(m0 + 8) * N + n0) = make_float2(v10, v11);
            } else {
                *(uint32_t*)(C16 + zC + (size_t)m0 * N + n0)       = pkh(v00, v01);
                *(uint32_t*)(C16 + zC + (size_t)(m0 + 8) * N + n0) = pkh(v10, v11);
            }
        }
    }
}

// ---------------------------------------------------------------------------
// Critical-path conversions only: z in {0,1}: x halves -> (xh, xl);
//                                  z = 2: Wq -> hi/lo; z = 3: Wk -> hi/lo.
// ---------------------------------------------------------------------------
__global__ __launch_bounds__(256)
void split_qk(const float* __restrict__ x, const float* __restrict__ Wq,
              const float* __restrict__ Wk,
              bf16* __restrict__ xh,  bf16* __restrict__ xl,
              bf16* __restrict__ Wqh, bf16* __restrict__ Wql,
              bf16* __restrict__ Wkh, bf16* __restrict__ Wkl)
{
    const int z = blockIdx.z;
    const float* in; bf16 *hi, *lo; size_t base, n4;
    if (z < 2) { in = x;  hi = xh;  lo = xl;  base = (size_t)z * (NX / 8); n4 = NX / 8; }
    else if (z == 2) { in = Wq; hi = Wqh; lo = Wql; base = 0; n4 = NW / 4; }
    else             { in = Wk; hi = Wkh; lo = Wkl; base = 0; n4 = NW / 4; }
    for (size_t i = (size_t)blockIdx.x * blockDim.x + threadIdx.x; i < n4;
         i += (size_t)gridDim.x * blockDim.x) {
        const size_t j = base + i;
        float4 v = ((const float4*)in)[j];
        bf16 h0, h1, h2, h3, l0, l1, l2, l3;
        split1(v.x, h0, l0); split1(v.y, h1, l1);
        split1(v.z, h2, l2); split1(v.w, h3, l3);
        ((uint2*)hi)[j] = make_uint2(pk(h0, h1), pk(h2, h3));
        ((uint2*)lo)[j] = make_uint2(pk(l0, l1), pk(l2, l3));
    }
}

// ---------------------------------------------------------------------------
// Side-stream conversions: z = 0: x -> xf (fp16); z = 1: Wv -> Wvf (fp16).
// ---------------------------------------------------------------------------
__global__ __launch_bounds__(256)
void conv_f16(const float* __restrict__ x, const float* __restrict__ Wv,
              __half* __restrict__ xf, __half* __restrict__ Wvf)
{
    const float* in; __half* outp; size_t n4;
    if (blockIdx.z == 0) { in = x;  outp = xf;  n4 = NX / 4; }
    else                 { in = Wv; outp = Wvf; n4 = NW / 4; }
    for (size_t i = (size_t)blockIdx.x * blockDim.x + threadIdx.x; i < n4;
         i += (size_t)gridDim.x * blockDim.x) {
        float4 v = ((const float4*)in)[i];
        ((uint2*)outp)[i] = make_uint2(pkh(v.x, v.y), pkh(v.z, v.w));
    }
}

// ---------------------------------------------------------------------------
// fp16 transpose (z = batch): Vt[b][d][s] = V[b][s][d]
// ---------------------------------------------------------------------------
__global__ __launch_bounds__(256)
void transpose_vf(const __half* __restrict__ V, __half* __restrict__ Vt)
{
    __shared__ __half t[32][33];
    const int b  = blockIdx.z;
    const __half* src = V  + (size_t)b * SEQ * DIM;
    __half*       dst = Vt + (size_t)b * SEQ * DIM;
    const int d0 = blockIdx.x * 32;
    const int s0 = blockIdx.y * 32;
    const int tx = threadIdx.x;
    const int ty = threadIdx.y;
    #pragma unroll
    for (int j = 0; j < 32; j += 8)
        t[ty + j][tx] = src[(size_t)(s0 + ty + j) * DIM + d0 + tx];
    __syncthreads();
    #pragma unroll
    for (int j = 0; j < 32; j += 8)
        dst[(size_t)(d0 + ty + j) * SEQ + s0 + tx] = t[tx][ty + j];
}

// ---------------------------------------------------------------------------
// Row softmax over SEQ=2048 -> fp16 probabilities (UNscaled; NORM folded into AV).
// ---------------------------------------------------------------------------
__global__ __launch_bounds__(256)
void softmax_f16(const float* __restrict__ S, __half* __restrict__ Pf)
{
    const float* row = S + (size_t)blockIdx.x * SEQ;
    const int tid = threadIdx.x;

    float4 v0 = *(const float4*)(row + tid * 4);
    float4 v1 = *(const float4*)(row + 1024 + tid * 4);

    float m = fmaxf(fmaxf(fmaxf(v0.x, v0.y), fmaxf(v0.z, v0.w)),
                    fmaxf(fmaxf(v1.x, v1.y), fmaxf(v1.z, v1.w)));
    #pragma unroll
    for (int o = 16; o > 0; o >>= 1)
        m = fmaxf(m, __shfl_xor_sync(0xffffffffu, m, o));

    __shared__ float red[8];
    const int wid = tid >> 5, lane = tid & 31;
    if (lane == 0) red[wid] = m;
    __syncthreads();
    m = red[0];
    #pragma unroll
    for (int w = 1; w < 8; w++) m = fmaxf(m, red[w]);

    v0.x = __expf(v0.x - m); v0.y = __expf(v0.y - m);
    v0.z = __expf(v0.z - m); v0.w = __expf(v0.w - m);
    v1.x = __expf(v1.x - m); v1.y = __expf(v1.y - m);
    v1.z = __expf(v1.z - m); v1.w = __expf(v1.w - m);

    float s = (v0.x + v0.y) + (v0.z + v0.w) + (v1.x + v1.y) + (v1.z + v1.w);
    #pragma unroll
    for (int o = 16; o > 0; o >>= 1)
        s += __shfl_xor_sync(0xffffffffu, s, o);

    __shared__ float red2[8];
    if (lane == 0) red2[wid] = s;
    __syncthreads();
    s = red2[0];
    #pragma unroll
    for (int w = 1; w < 8; w++) s += red2[w];

    const float scale = 1.0f / s;      // NORM_FACT applied in AV epilogue
    v0.x *= scale; v0.y *= scale; v0.z *= scale; v0.w *= scale;
    v1.x *= scale; v1.y *= scale; v1.z *= scale; v1.w *= scale;

    __half* ph = Pf + (size_t)blockIdx.x * SEQ;
    *(uint2*)(ph + tid * 4)        = make_uint2(pkh(v0.x, v0.y), pkh(v0.z, v0.w));
    *(uint2*)(ph + 1024 + tid * 4) = make_uint2(pkh(v1.x, v1.y), pkh(v1.z, v1.w));
}

// ---------------------------------------------------------------------------
extern "C" void kernel_launch(void* const* d_in, const int* in_sizes, int n_in,
                              void* d_out, int out_size)
{
    const float* x  = (const float*)d_in[0];
    const float* Wq = (const float*)d_in[1];
    const float* bq = (const float*)d_in[2];
    const float* Wk = (const float*)d_in[3];
    const float* bk = (const float*)d_in[4];
    const float* Wv = (const float*)d_in[5];
    const float* bv = (const float*)d_in[6];
    float* out = (float*)d_out;

    bf16 *xh, *xl, *Wqh, *Wql, *Wkh, *Wkl;
    bf16 *Qh, *Ql, *Kh, *Kl;
    __half *xf, *Wvf, *Vf, *Vtf, *Pf;
    float* P;
    cudaGetSymbolAddress((void**)&xh,  g_xh);  cudaGetSymbolAddress((void**)&xl,  g_xl);
    cudaGetSymbolAddress((void**)&Wqh, g_Wqh); cudaGetSymbolAddress((void**)&Wql, g_Wql);
    cudaGetSymbolAddress((void**)&Wkh, g_Wkh); cudaGetSymbolAddress((void**)&Wkl, g_Wkl);
    cudaGetSymbolAddress((void**)&Qh,  g_Qh);  cudaGetSymbolAddress((void**)&Ql,  g_Ql);
    cudaGetSymbolAddress((void**)&Kh,  g_Kh);  cudaGetSymbolAddress((void**)&Kl,  g_Kl);
    cudaGetSymbolAddress((void**)&xf,  g_xf);
    cudaGetSymbolAddress((void**)&Wvf, g_Wvf);
    cudaGetSymbolAddress((void**)&Vf,  g_Vf);
    cudaGetSymbolAddress((void**)&Vtf, g_Vtf);
    cudaGetSymbolAddress((void**)&Pf,  g_Pf);
    cudaGetSymbolAddress((void**)&P,   g_P);

    cudaFuncSetAttribute(gemm_sp,  cudaFuncAttributeMaxDynamicSharedMemorySize, SMEM_TOTAL);
    cudaFuncSetAttribute(gemm_qkv, cudaFuncAttributeMaxDynamicSharedMemorySize, SMEM_TOTAL);
    cudaFuncSetAttribute(gemm_h16, cudaFuncAttributeMaxDynamicSharedMemorySize, SMEM_AV);

    // One-time side stream + events (host resources, no device memory).
    static cudaStream_t s1 = nullptr;
    static cudaEvent_t eFork = nullptr, eJoin = nullptr;
    if (!s1) {
        cudaStreamCreateWithFlags(&s1, cudaStreamNonBlocking);
        cudaEventCreateWithFlags(&eFork, cudaEventDisableTiming);
        cudaEventCreateWithFlags(&eJoin, cudaEventDisableTiming);
    }

    // Fork immediately: the s1 V-pipeline depends only on raw inputs.
    cudaEventRecord(eFork, 0);
    cudaStreamWaitEvent(s1, eFork, 0);

    // s1: x/Wv -> fp16, V projection, V transpose (hidden under the main chain)
    {
        dim3 cgrid(1024, 1, 2);
        conv_f16<<<cgrid, 256, 0, s1>>>(x, Wv, xf, Wvf);
        dim3 vgrid(DIM / 128, (BATCH * SEQ) / 128, 1);
        gemm_h16<<<vgrid, 256, SMEM_AV, s1>>>(xf, Wvf, bv, nullptr, Vf, 1.0f,
                                              BATCH * SEQ, DIM, DIM, 0, 0, 0);
        dim3 tgrid(DIM / 32, SEQ / 32, BATCH);
        transpose_vf<<<tgrid, dim3(32, 8), 0, s1>>>(Vf, Vtf);
        cudaEventRecord(eJoin, s1);
    }

    // main: critical-path conversions (x hi/lo halves, Wq, Wk)
    {
        dim3 grid(1024, 1, 4);
        split_qk<<<grid, 256>>>(x, Wq, Wk, xh, xl, Wqh, Wql, Wkh, Wkl);
    }

    // main: Q/K projections (3-term split path, z = {Q,K})
    {
        dim3 grid(DIM / 128, (BATCH * SEQ) / 128, 2);
        gemm_qkv<<<grid, 256, SMEM_TOTAL>>>(xh, xl, Wqh, Wql, Wkh, Wkl,
                                            bq, bk, Qh, Ql, Kh, Kl);
    }

    // main: scores[b] = Q[b] @ K[b]^T  -> fp32 P
    {
        dim3 grid(SEQ / 128, SEQ / 128, BATCH);
        gemm_sp<<<grid, 256, SMEM_TOTAL>>>(Qh, Ql, Kh, Kl, P,
                                           SEQ, SEQ, DIM,
                                           (size_t)SEQ * DIM, (size_t)SEQ * DIM,
                                           (size_t)SEQ * SEQ);
    }

    // main: softmax rows -> fp16 P (unscaled)
    softmax_f16<<<BATCH * SEQ, 256>>>(P, Pf);

    // Join: AV needs Vtf from s1.
    cudaStreamWaitEvent(0, eJoin, 0);

    // main: out[b] = NORM * (P[b] @ Vt[b]^T)
    {
        dim3 grid(DIM / 128, SEQ / 128, BATCH);
        gemm_h16<<<grid, 256, SMEM_AV>>>(Pf, Vtf, nullptr, out, nullptr, NORM_FACT,
                                         SEQ, DIM, SEQ,
                                         (size_t)SEQ * SEQ, (size_t)SEQ * DIM,
                                         (size_t)SEQ * DIM);
    }
}

// round 15
// speedup vs baseline: 1.0368x; 1.0304x over previous
#include <cuda_runtime.h>
#include <cuda_bf16.h>
#include <cuda_fp16.h>
#include <cstdint>

#define BATCH 4
#define SEQ   2048
#define DIM   1024
#define NORM_FACT 0.03125f   // 1/sqrt(1024), applied POST-softmax per reference

typedef __nv_bfloat16 bf16;

// ---------------------------------------------------------------------------
// Scratch (allocation-free rule: __device__ globals).
// Q/K pre-split bf16 hi/lo (3-term path); x/Wv/V/P fp16 (1-term paths).
// ---------------------------------------------------------------------------
#define NX  ((size_t)BATCH * SEQ * DIM)   // 8M
#define NW  ((size_t)DIM * DIM)           // 1M
#define NP  ((size_t)BATCH * SEQ * SEQ)   // 16M

__device__ __align__(256) bf16 g_xh[NX],  g_xl[NX];
__device__ __align__(256) bf16 g_Wqh[NW], g_Wql[NW];
__device__ __align__(256) bf16 g_Wkh[NW], g_Wkl[NW];
__device__ __align__(256) bf16 g_Qh[NX],  g_Ql[NX];
__device__ __align__(256) bf16 g_Kh[NX],  g_Kl[NX];
__device__ __align__(256) __half g_xf[NX];
__device__ __align__(256) __half g_Wvf[NW];
__device__ __align__(256) __half g_Vf[NX];
__device__ __align__(256) __half g_Vtf[NX];
__device__ __align__(256) __half g_Pf[NP];
__device__ __align__(256) float  g_P[NP];

// ---------------------------------------------------------------------------
// Smem layouts. Row stride 80 B -> ldmatrix conflict-free, cp.async 16B-aligned.
// ---------------------------------------------------------------------------
#define ROWB   80
#define TILEB  (128 * ROWB)          // 10240
#define STAGE  (4 * TILEB)           // 40960
#define SMEM_TOTAL (2 * STAGE)       // 81920
#define STAV   (2 * TILEB)           // 20480
#define SMEM_AV (2 * STAV)           // 40960

extern __shared__ char dsm[];

__device__ __forceinline__ uint32_t smem_u32(const void* p) {
    uint32_t a;
    asm("{ .reg .u64 t; cvta.to.shared.u64 t, %1; cvt.u32.u64 %0, t; }"
        : "=r"(a) : "l"(p));
    return a;
}

#define CPA16(dst, src) \
    asm volatile("cp.async.cg.shared.global [%0], [%1], 16;" :: "r"(dst), "l"(src))
#define CPA_COMMIT() asm volatile("cp.async.commit_group;" ::: "memory")
#define CPA_WAIT0()  asm volatile("cp.async.wait_group 0;" ::: "memory")

#define LDSM4(R, addr)                                                        \
    asm volatile("ldmatrix.sync.aligned.m8n8.x4.shared.b16 {%0,%1,%2,%3}, [%4];" \
                 : "=r"((R)[0]), "=r"((R)[1]), "=r"((R)[2]), "=r"((R)[3])     \
                 : "r"(addr))

#define MMA(cc, A, b0, b1)                                                    \
    asm volatile("mma.sync.aligned.m16n8k16.row.col.f32.bf16.bf16.f32 "       \
                 "{%0,%1,%2,%3},{%4,%5,%6,%7},{%8,%9},{%0,%1,%2,%3};"         \
                 : "+f"((cc)[0]), "+f"((cc)[1]), "+f"((cc)[2]), "+f"((cc)[3]) \
                 : "r"((A)[0]), "r"((A)[1]), "r"((A)[2]), "r"((A)[3]),        \
                   "r"(b0), "r"(b1))

#define MMA_F16(cc, A, b0, b1)                                                \
    asm volatile("mma.sync.aligned.m16n8k16.row.col.f32.f16.f16.f32 "         \
                 "{%0,%1,%2,%3},{%4,%5,%6,%7},{%8,%9},{%0,%1,%2,%3};"         \
                 : "+f"((cc)[0]), "+f"((cc)[1]), "+f"((cc)[2]), "+f"((cc)[3]) \
                 : "r"((A)[0]), "r"((A)[1]), "r"((A)[2]), "r"((A)[3]),        \
                   "r"(b0), "r"(b1))

__device__ __forceinline__ uint32_t pk(bf16 a, bf16 b) {
    return (uint32_t)__bfloat16_as_ushort(a) | ((uint32_t)__bfloat16_as_ushort(b) << 16);
}

__device__ __forceinline__ uint32_t pkh(float a, float b) {
    __half2 h = __floats2half2_rn(a, b);
    return *(uint32_t*)&h;
}

__device__ __forceinline__ void split1(float v, bf16& h, bf16& l) {
    h = __float2bfloat16_rn(v);
    l = __float2bfloat16_rn(v - __bfloat162float(h));
}

// ---------------------------------------------------------------------------
// 3-term split-precision NT GEMM body (validated R7 structure).
// ---------------------------------------------------------------------------
__device__ __forceinline__
void gemm_body(const bf16* __restrict__ Ah, const bf16* __restrict__ Al,
               const bf16* __restrict__ Bh, const bf16* __restrict__ Bl,
               const float* __restrict__ bias,
               float* __restrict__ Cf, bf16* __restrict__ Ch, bf16* __restrict__ Cl,
               int M, int N, int K, int bm, int bn)
{
    const int tid  = threadIdx.x;
    const int wid  = tid >> 5;
    const int lane = tid & 31;
    const int wm   = wid >> 2;
    const int wn   = wid & 3;

    const int lrow  = tid >> 1;
    const int lsegB = (tid & 1) * 32;
    const uint32_t so = (uint32_t)lrow * ROWB + (uint32_t)lsegB;
    const bf16* pAh = Ah + (size_t)(bm + lrow) * K + lsegB / 2;
    const bf16* pAl = Al + (size_t)(bm + lrow) * K + lsegB / 2;
    const bf16* pBh = Bh + (size_t)(bn + lrow) * K + lsegB / 2;
    const bf16* pBl = Bl + (size_t)(bn + lrow) * K + lsegB / 2;

    const uint32_t sb = smem_u32(dsm);
    const uint32_t laneOff = (uint32_t)(lane & 15) * ROWB + (uint32_t)(lane >> 4) * 16;

    float acc[4][4][4] = {};

    {
        const uint32_t s0 = sb;
        CPA16(s0 + 0 * TILEB + so,      pAh);
        CPA16(s0 + 0 * TILEB + so + 16, pAh + 8);
        CPA16(s0 + 1 * TILEB + so,      pAl);
        CPA16(s0 + 1 * TILEB + so + 16, pAl + 8);
        CPA16(s0 + 2 * TILEB + so,      pBh);
        CPA16(s0 + 2 * TILEB + so + 16, pBh + 8);
        CPA16(s0 + 3 * TILEB + so,      pBl);
        CPA16(s0 + 3 * TILEB + so + 16, pBl + 8);
        CPA_COMMIT();
    }

    const int NC = K >> 5;
    for (int c = 0; c < NC; c++) {
        CPA_WAIT0();
        __syncthreads();

        if (c + 1 < NC) {
            const int k1 = (c + 1) << 5;
            const uint32_t s1 = sb + (uint32_t)((c + 1) & 1) * STAGE;
            CPA16(s1 + 0 * TILEB + so,      pAh + k1);
            CPA16(s1 + 0 * TILEB + so + 16, pAh + k1 + 8);
            CPA16(s1 + 1 * TILEB + so,      pAl + k1);
            CPA16(s1 + 1 * TILEB + so + 16, pAl + k1 + 8);
            CPA16(s1 + 2 * TILEB + so,      pBh + k1);
            CPA16(s1 + 2 * TILEB + so + 16, pBh + k1 + 8);
            CPA16(s1 + 3 * TILEB + so,      pBl + k1);
            CPA16(s1 + 3 * TILEB + so + 16, pBl + k1 + 8);
            CPA_COMMIT();
        }

        const uint32_t sbase = sb + (uint32_t)(c & 1) * STAGE;
        const uint32_t aH = sbase + 0 * TILEB + (uint32_t)wm * 64 * ROWB + laneOff;
        const uint32_t aL = aH + TILEB;
        const uint32_t bH = sbase + 2 * TILEB + (uint32_t)wn * 32 * ROWB + laneOff;
        const uint32_t bL = bH + TILEB;

        #pragma unroll
        for (int ks = 0; ks < 2; ks++) {
            const uint32_t ko = ks * 32;
            uint32_t a[4][4], bh[2][4], bl[2][4];
            LDSM4(bh[0], bH + ko);
            LDSM4(bh[1], bH + 16 * ROWB + ko);
            LDSM4(bl[0], bL + ko);
            LDSM4(bl[1], bL + 16 * ROWB + ko);
            #pragma unroll
            for (int mt = 0; mt < 4; mt++) LDSM4(a[mt], aH + mt * 16 * ROWB + ko);

            #pragma unroll
            for (int mt = 0; mt < 4; mt++)
                #pragma unroll
                for (int nt = 0; nt < 4; nt++)
                    MMA(acc[mt][nt], a[mt], bh[nt >> 1][nt & 1], bh[nt >> 1][(nt & 1) + 2]);
            #pragma unroll
            for (int mt = 0; mt < 4; mt++)
                #pragma unroll
                for (int nt = 0; nt < 4; nt++)
                    MMA(acc[mt][nt], a[mt], bl[nt >> 1][nt & 1], bl[nt >> 1][(nt & 1) + 2]);

            #pragma unroll
            for (int mt = 0; mt < 4; mt++) LDSM4(a[mt], aL + mt * 16 * ROWB + ko);
            #pragma unroll
            for (int mt = 0; mt < 4; mt++)
                #pragma unroll
                for (int nt = 0; nt < 4; nt++)
                    MMA(acc[mt][nt], a[mt], bh[nt >> 1][nt & 1], bh[nt >> 1][(nt & 1) + 2]);
        }
    }

    const int lr = lane >> 2;
    const int lc = (lane & 3) * 2;
    #pragma unroll
    for (int mt = 0; mt < 4; mt++) {
        const int m0 = bm + wm * 64 + mt * 16 + lr;
        #pragma unroll
        for (int nt = 0; nt < 4; nt++) {
            const int n0 = bn + wn * 32 + nt * 8 + lc;
            float bx = 0.f, by = 0.f;
            if (bias) { bx = bias[n0]; by = bias[n0 + 1]; }
            float v00 = acc[mt][nt][0] + bx, v01 = acc[mt][nt][1] + by;
            float v10 = acc[mt][nt][2] + bx, v11 = acc[mt][nt][3] + by;
            if (Cf) {
                *(float2*)(Cf + (size_t)m0 * N + n0)       = make_float2(v00, v01);
                *(float2*)(Cf + (size_t)(m0 + 8) * N + n0) = make_float2(v10, v11);
            } else {
                bf16 h0, h1, l0, l1;
                split1(v00, h0, l0); split1(v01, h1, l1);
                *(uint32_t*)(Ch + (size_t)m0 * N + n0) = pk(h0, h1);
                *(uint32_t*)(Cl + (size_t)m0 * N + n0) = pk(l0, l1);
                split1(v10, h0, l0); split1(v11, h1, l1);
                *(uint32_t*)(Ch + (size_t)(m0 + 8) * N + n0) = pk(h0, h1);
                *(uint32_t*)(Cl + (size_t)(m0 + 8) * N + n0) = pk(l0, l1);
            }
        }
    }
}

// Batched QK^T GEMM -> fp32 scores.
__global__ __launch_bounds__(256, 2)
void gemm_sp(const bf16* __restrict__ Ah, const bf16* __restrict__ Al,
             const bf16* __restrict__ Bh, const bf16* __restrict__ Bl,
             float* __restrict__ Cf,
             int M, int N, int K, size_t sA, size_t sB, size_t sC)
{
    const size_t zA = (size_t)blockIdx.z * sA;
    const size_t zB = (size_t)blockIdx.z * sB;
    const size_t zC = (size_t)blockIdx.z * sC;
    gemm_body(Ah + zA, Al + zA, Bh + zB, Bl + zB, nullptr,
              Cf + zC, nullptr, nullptr,
              M, N, K, blockIdx.y * 128, blockIdx.x * 128);
}

// Fused Q/K projection: z selects {Q, K} (split bf16 outputs).
__global__ __launch_bounds__(256, 2)
void gemm_qkv(const bf16* __restrict__ xh, const bf16* __restrict__ xl,
              const bf16* __restrict__ Wqh, const bf16* __restrict__ Wql,
              const bf16* __restrict__ Wkh, const bf16* __restrict__ Wkl,
              const float* __restrict__ bq, const float* __restrict__ bk,
              bf16* __restrict__ Qh, bf16* __restrict__ Ql,
              bf16* __restrict__ Kh, bf16* __restrict__ Kl)
{
    const bf16 *Bh, *Bl; const float* bias; bf16 *Ch, *Cl;
    if (blockIdx.z == 0) { Bh = Wqh; Bl = Wql; bias = bq; Ch = Qh; Cl = Ql; }
    else                 { Bh = Wkh; Bl = Wkl; bias = bk; Ch = Kh; Cl = Kl; }
    gemm_body(xh, xl, Bh, Bl, bias, nullptr, Ch, Cl,
              BATCH * SEQ, DIM, DIM, blockIdx.y * 128, blockIdx.x * 128);
}

// ---------------------------------------------------------------------------
// Single-term fp16 NT GEMM: C[M,N] = scale * (A[M,K] * B[N,K]^T) (+ bias).
// ---------------------------------------------------------------------------
__global__ __launch_bounds__(256, 2)
void gemm_h16(const __half* __restrict__ A, const __half* __restrict__ B,
              const float* __restrict__ bias,
              float* __restrict__ Cf, __half* __restrict__ C16, float scale,
              int M, int N, int K, size_t sA, size_t sB, size_t sC)
{
    const __half* Az = A + (size_t)blockIdx.z * sA;
    const __half* Bz = B + (size_t)blockIdx.z * sB;
    const size_t  zC = (size_t)blockIdx.z * sC;

    const int tid  = threadIdx.x;
    const int wid  = tid >> 5;
    const int lane = tid & 31;
    const int wm   = wid >> 2;
    const int wn   = wid & 3;
    const int bm = blockIdx.y * 128;
    const int bn = blockIdx.x * 128;

    const int lrow  = tid >> 1;
    const int lsegB = (tid & 1) * 32;
    const uint32_t so = (uint32_t)lrow * ROWB + (uint32_t)lsegB;
    const __half* pA = Az + (size_t)(bm + lrow) * K + lsegB / 2;
    const __half* pB = Bz + (size_t)(bn + lrow) * K + lsegB / 2;

    const uint32_t sb = smem_u32(dsm);
    const uint32_t laneOff = (uint32_t)(lane & 15) * ROWB + (uint32_t)(lane >> 4) * 16;

    float acc[4][4][4] = {};

    {
        CPA16(sb + so,              pA);
        CPA16(sb + so + 16,         pA + 8);
        CPA16(sb + TILEB + so,      pB);
        CPA16(sb + TILEB + so + 16, pB + 8);
        CPA_COMMIT();
    }

    const int NC = K >> 5;
    for (int c = 0; c < NC; c++) {
        CPA_WAIT0();
        __syncthreads();

        if (c + 1 < NC) {
            const int k1 = (c + 1) << 5;
            const uint32_t s1 = sb + (uint32_t)((c + 1) & 1) * STAV;
            CPA16(s1 + so,              pA + k1);
            CPA16(s1 + so + 16,         pA + k1 + 8);
            CPA16(s1 + TILEB + so,      pB + k1);
            CPA16(s1 + TILEB + so + 16, pB + k1 + 8);
            CPA_COMMIT();
        }

        const uint32_t sbase = sb + (uint32_t)(c & 1) * STAV;
        const uint32_t aB = sbase + (uint32_t)wm * 64 * ROWB + laneOff;
        const uint32_t bB = sbase + TILEB + (uint32_t)wn * 32 * ROWB + laneOff;

        #pragma unroll
        for (int ks = 0; ks < 2; ks++) {
            const uint32_t ko = ks * 32;
            uint32_t a[4][4], b[2][4];
            LDSM4(b[0], bB + ko);
            LDSM4(b[1], bB + 16 * ROWB + ko);
            #pragma unroll
            for (int mt = 0; mt < 4; mt++) LDSM4(a[mt], aB + mt * 16 * ROWB + ko);
            #pragma unroll
            for (int mt = 0; mt < 4; mt++)
                #pragma unroll
                for (int nt = 0; nt < 4; nt++)
                    MMA_F16(acc[mt][nt], a[mt], b[nt >> 1][nt & 1], b[nt >> 1][(nt & 1) + 2]);
        }
    }

    const int lr = lane >> 2;
    const int lc = (lane & 3) * 2;
    #pragma unroll
    for (int mt = 0; mt < 4; mt++) {
        const int m0 = bm + wm * 64 + mt * 16 + lr;
        #pragma unroll
        for (int nt = 0; nt < 4; nt++) {
            const int n0 = bn + wn * 32 + nt * 8 + lc;
            float bx = 0.f, by = 0.f;
            if (bias) { bx = bias[n0]; by = bias[n0 + 1]; }
            float v00 = acc[mt][nt][0] * scale + bx, v01 = acc[mt][nt][1] * scale + by;
            float v10 = acc[mt][nt][2] * scale + bx, v11 = acc[mt][nt][3] * scale + by;
            if (Cf) {
                *(float2*)(Cf + zC + (size_t)m0 * N + n0)       = make_float2(v00, v01);
                *(float2*)(Cf + zC + (size_t)(m0 + 8) * N + n0) = make_float2(v10, v11);
            } else {
                *(uint32_t*)(C16 + zC + (size_t)m0 * N + n0)       = pkh(v00, v01);
                *(uint32_t*)(C16 + zC + (size_t)(m0 + 8) * N + n0) = pkh(v10, v11);
            }
        }
    }
}

// ---------------------------------------------------------------------------
// Merged fp32 conversions, LOAD-BALANCED across z:
//   z in {0..3}: x quarter -> (xh, xl, xf) in one pass (x read once)
//   z = 4: Wq -> hi/lo;  z = 5: Wk -> hi/lo;  z = 6: Wv -> fp16
// ---------------------------------------------------------------------------
__global__ __launch_bounds__(256)
void split_all(const float* __restrict__ x,  const float* __restrict__ Wq,
               const float* __restrict__ Wk, const float* __restrict__ Wv,
               bf16* __restrict__ xh,  bf16* __restrict__ xl, __half* __restrict__ xf,
               bf16* __restrict__ Wqh, bf16* __restrict__ Wql,
               bf16* __restrict__ Wkh, bf16* __restrict__ Wkl,
               __half* __restrict__ Wvf)
{
    const int z = blockIdx.z;
    if (z < 4) {
        const size_t base = (size_t)z * (NX / 16);  // quarter of x, in float4s
        const size_t n4   = NX / 16;
        for (size_t i = (size_t)blockIdx.x * blockDim.x + threadIdx.x; i < n4;
             i += (size_t)gridDim.x * blockDim.x) {
            const size_t j = base + i;
            float4 v = ((const float4*)x)[j];
            bf16 h0, h1, h2, h3, l0, l1, l2, l3;
            split1(v.x, h0, l0); split1(v.y, h1, l1);
            split1(v.z, h2, l2); split1(v.w, h3, l3);
            ((uint2*)xh)[j] = make_uint2(pk(h0, h1), pk(h2, h3));
            ((uint2*)xl)[j] = make_uint2(pk(l0, l1), pk(l2, l3));
            ((uint2*)xf)[j] = make_uint2(pkh(v.x, v.y), pkh(v.z, v.w));
        }
        return;
    }
    if (z == 6) {
        for (size_t i = (size_t)blockIdx.x * blockDim.x + threadIdx.x; i < NW / 4;
             i += (size_t)gridDim.x * blockDim.x) {
            float4 v = ((const float4*)Wv)[i];
            ((uint2*)Wvf)[i] = make_uint2(pkh(v.x, v.y), pkh(v.z, v.w));
        }
        return;
    }
    const float* in; bf16 *hi, *lo;
    if (z == 4) { in = Wq; hi = Wqh; lo = Wql; }
    else        { in = Wk; hi = Wkh; lo = Wkl; }
    for (size_t i = (size_t)blockIdx.x * blockDim.x + threadIdx.x; i < NW / 4;
         i += (size_t)gridDim.x * blockDim.x) {
        float4 v = ((const float4*)in)[i];
        bf16 h0, h1, h2, h3, l0, l1, l2, l3;
        split1(v.x, h0, l0); split1(v.y, h1, l1);
        split1(v.z, h2, l2); split1(v.w, h3, l3);
        ((uint2*)hi)[i] = make_uint2(pk(h0, h1), pk(h2, h3));
        ((uint2*)lo)[i] = make_uint2(pk(l0, l1), pk(l2, l3));
    }
}

// ---------------------------------------------------------------------------
// fp16 transpose (z = batch): Vt[b][d][s] = V[b][s][d]
// ---------------------------------------------------------------------------
__global__ __launch_bounds__(256)
void transpose_vf(const __half* __restrict__ V, __half* __restrict__ Vt)
{
    __shared__ __half t[32][33];
    const int b  = blockIdx.z;
    const __half* src = V  + (size_t)b * SEQ * DIM;
    __half*       dst = Vt + (size_t)b * SEQ * DIM;
    const int d0 = blockIdx.x * 32;
    const int s0 = blockIdx.y * 32;
    const int tx = threadIdx.x;
    const int ty = threadIdx.y;
    #pragma unroll
    for (int j = 0; j < 32; j += 8)
        t[ty + j][tx] = src[(size_t)(s0 + ty + j) * DIM + d0 + tx];
    __syncthreads();
    #pragma unroll
    for (int j = 0; j < 32; j += 8)
        dst[(size_t)(d0 + ty + j) * SEQ + s0 + tx] = t[tx][ty + j];
}

// ---------------------------------------------------------------------------
// Row softmax over SEQ=2048 -> fp16 probabilities (UNscaled; NORM folded into AV).
// ---------------------------------------------------------------------------
__global__ __launch_bounds__(256)
void softmax_f16(const float* __restrict__ S, __half* __restrict__ Pf)
{
    const float* row = S + (size_t)blockIdx.x * SEQ;
    const int tid = threadIdx.x;

    float4 v0 = *(const float4*)(row + tid * 4);
    float4 v1 = *(const float4*)(row + 1024 + tid * 4);

    float m = fmaxf(fmaxf(fmaxf(v0.x, v0.y), fmaxf(v0.z, v0.w)),
                    fmaxf(fmaxf(v1.x, v1.y), fmaxf(v1.z, v1.w)));
    #pragma unroll
    for (int o = 16; o > 0; o >>= 1)
        m = fmaxf(m, __shfl_xor_sync(0xffffffffu, m, o));

    __shared__ float red[8];
    const int wid = tid >> 5, lane = tid & 31;
    if (lane == 0) red[wid] = m;
    __syncthreads();
    m = red[0];
    #pragma unroll
    for (int w = 1; w < 8; w++) m = fmaxf(m, red[w]);

    v0.x = __expf(v0.x - m); v0.y = __expf(v0.y - m);
    v0.z = __expf(v0.z - m); v0.w = __expf(v0.w - m);
    v1.x = __expf(v1.x - m); v1.y = __expf(v1.y - m);
    v1.z = __expf(v1.z - m); v1.w = __expf(v1.w - m);

    float s = (v0.x + v0.y) + (v0.z + v0.w) + (v1.x + v1.y) + (v1.z + v1.w);
    #pragma unroll
    for (int o = 16; o > 0; o >>= 1)
        s += __shfl_xor_sync(0xffffffffu, s, o);

    __shared__ float red2[8];
    if (lane == 0) red2[wid] = s;
    __syncthreads();
    s = red2[0];
    #pragma unroll
    for (int w = 1; w < 8; w++) s += red2[w];

    const float scale = 1.0f / s;      // NORM_FACT applied in AV epilogue
    v0.x *= scale; v0.y *= scale; v0.z *= scale; v0.w *= scale;
    v1.x *= scale; v1.y *= scale; v1.z *= scale; v1.w *= scale;

    __half* ph = Pf + (size_t)blockIdx.x * SEQ;
    *(uint2*)(ph + tid * 4)        = make_uint2(pkh(v0.x, v0.y), pkh(v0.z, v0.w));
    *(uint2*)(ph + 1024 + tid * 4) = make_uint2(pkh(v1.x, v1.y), pkh(v1.z, v1.w));
}

// ---------------------------------------------------------------------------
extern "C" void kernel_launch(void* const* d_in, const int* in_sizes, int n_in,
                              void* d_out, int out_size)
{
    const float* x  = (const float*)d_in[0];
    const float* Wq = (const float*)d_in[1];
    const float* bq = (const float*)d_in[2];
    const float* Wk = (const float*)d_in[3];
    const float* bk = (const float*)d_in[4];
    const float* Wv = (const float*)d_in[5];
    const float* bv = (const float*)d_in[6];
    float* out = (float*)d_out;

    bf16 *xh, *xl, *Wqh, *Wql, *Wkh, *Wkl;
    bf16 *Qh, *Ql, *Kh, *Kl;
    __half *xf, *Wvf, *Vf, *Vtf, *Pf;
    float* P;
    cudaGetSymbolAddress((void**)&xh,  g_xh);  cudaGetSymbolAddress((void**)&xl,  g_xl);
    cudaGetSymbolAddress((void**)&Wqh, g_Wqh); cudaGetSymbolAddress((void**)&Wql, g_Wql);
    cudaGetSymbolAddress((void**)&Wkh, g_Wkh); cudaGetSymbolAddress((void**)&Wkl, g_Wkl);
    cudaGetSymbolAddress((void**)&Qh,  g_Qh);  cudaGetSymbolAddress((void**)&Ql,  g_Ql);
    cudaGetSymbolAddress((void**)&Kh,  g_Kh);  cudaGetSymbolAddress((void**)&Kl,  g_Kl);
    cudaGetSymbolAddress((void**)&xf,  g_xf);
    cudaGetSymbolAddress((void**)&Wvf, g_Wvf);
    cudaGetSymbolAddress((void**)&Vf,  g_Vf);
    cudaGetSymbolAddress((void**)&Vtf, g_Vtf);
    cudaGetSymbolAddress((void**)&Pf,  g_Pf);
    cudaGetSymbolAddress((void**)&P,   g_P);

    cudaFuncSetAttribute(gemm_sp,  cudaFuncAttributeMaxDynamicSharedMemorySize, SMEM_TOTAL);
    cudaFuncSetAttribute(gemm_qkv, cudaFuncAttributeMaxDynamicSharedMemorySize, SMEM_TOTAL);
    cudaFuncSetAttribute(gemm_h16, cudaFuncAttributeMaxDynamicSharedMemorySize, SMEM_AV);

    // One-time side stream + events (host resources, no device memory).
    static cudaStream_t s1 = nullptr;
    static cudaEvent_t eFork = nullptr, eJoin = nullptr;
    if (!s1) {
        cudaStreamCreateWithFlags(&s1, cudaStreamNonBlocking);
        cudaEventCreateWithFlags(&eFork, cudaEventDisableTiming);
        cudaEventCreateWithFlags(&eJoin, cudaEventDisableTiming);
    }

    // 0) conversions: x -> (bf16 hi/lo + fp16) in one pass, Wq/Wk -> hi/lo,
    //    Wv -> fp16. Balanced z-slices (x quartered).
    {
        dim3 grid(1024, 1, 7);
        split_all<<<grid, 256>>>(x, Wq, Wk, Wv, xh, xl, xf,
                                 Wqh, Wql, Wkh, Wkl, Wvf);
    }

    // Fork: side stream handles the V pipeline (independent of Q/K chain).
    cudaEventRecord(eFork, 0);
    cudaStreamWaitEvent(s1, eFork, 0);

    // 1a) Q/K projections (main stream, 3-term split path)
    {
        dim3 grid(DIM / 128, (BATCH * SEQ) / 128, 2);
        gemm_qkv<<<grid, 256, SMEM_TOTAL>>>(xh, xl, Wqh, Wql, Wkh, Wkl,
                                            bq, bk, Qh, Ql, Kh, Kl);
    }

    // 1b) V projection + transpose on side stream (overlaps Q/K proj + QK)
    {
        dim3 grid(DIM / 128, (BATCH * SEQ) / 128, 1);
        gemm_h16<<<grid, 256, SMEM_AV, s1>>>(xf, Wvf, bv, nullptr, Vf, 1.0f,
                                             BATCH * SEQ, DIM, DIM, 0, 0, 0);
        dim3 tgrid(DIM / 32, SEQ / 32, BATCH);
        transpose_vf<<<tgrid, dim3(32, 8), 0, s1>>>(Vf, Vtf);
        cudaEventRecord(eJoin, s1);
    }

    // 3) scores[b] = Q[b] @ K[b]^T  -> fp32 P (3-term split path)
    {
        dim3 grid(SEQ / 128, SEQ / 128, BATCH);
        gemm_sp<<<grid, 256, SMEM_TOTAL>>>(Qh, Ql, Kh, Kl, P,
                                           SEQ, SEQ, DIM,
                                           (size_t)SEQ * DIM, (size_t)SEQ * DIM,
                                           (size_t)SEQ * SEQ);
    }

    // 4) softmax rows -> fp16 P (unscaled)
    softmax_f16<<<BATCH * SEQ, 256>>>(P, Pf);

    // Join: AV needs Vtf from the side stream.
    cudaStreamWaitEvent(0, eJoin, 0);

    // 5) out[b] = NORM * (P[b] @ Vt[b]^T)  (single-term fp16 MMA)
    {
        dim3 grid(DIM / 128, SEQ / 128, BATCH);
        gemm_h16<<<grid, 256, SMEM_AV>>>(Pf, Vtf, nullptr, out, nullptr, NORM_FACT,
                                         SEQ, DIM, SEQ,
                                         (size_t)SEQ * SEQ, (size_t)SEQ * DIM,
                                         (size_t)SEQ * DIM);
    }
}

// round 16
// speedup vs baseline: 1.0410x; 1.0040x over previous
#include <cuda_runtime.h>
#include <cuda_bf16.h>
#include <cuda_fp16.h>
#include <cstdint>

#define BATCH 4
#define SEQ   2048
#define DIM   1024
#define NORM_FACT 0.03125f   // 1/sqrt(1024), applied POST-softmax per reference

typedef __nv_bfloat16 bf16;

// ---------------------------------------------------------------------------
// Scratch (allocation-free rule: __device__ globals).
// Q/K pre-split bf16 hi/lo (3-term path); x/Wv/V/P fp16 (1-term paths).
// ---------------------------------------------------------------------------
#define NX  ((size_t)BATCH * SEQ * DIM)   // 8M
#define NW  ((size_t)DIM * DIM)           // 1M
#define NP  ((size_t)BATCH * SEQ * SEQ)   // 16M

__device__ __align__(256) bf16 g_xh[NX],  g_xl[NX];
__device__ __align__(256) bf16 g_Wqh[NW], g_Wql[NW];
__device__ __align__(256) bf16 g_Wkh[NW], g_Wkl[NW];
__device__ __align__(256) bf16 g_Qh[NX],  g_Ql[NX];
__device__ __align__(256) bf16 g_Kh[NX],  g_Kl[NX];
__device__ __align__(256) __half g_xf[NX];
__device__ __align__(256) __half g_Wvf[NW];
__device__ __align__(256) __half g_Vf[NX];
__device__ __align__(256) __half g_Vtf[NX];
__device__ __align__(256) __half g_Pf[NP];
__device__ __align__(256) float  g_P[NP];

// ---------------------------------------------------------------------------
// Smem layouts. Row stride 80 B -> ldmatrix conflict-free, cp.async 16B-aligned.
// ---------------------------------------------------------------------------
#define ROWB   80
#define TILEB  (128 * ROWB)          // 10240
#define STAGE  (4 * TILEB)           // 40960
#define SMEM_TOTAL (2 * STAGE)       // 81920
#define STAV   (2 * TILEB)           // 20480
#define SMEM_AV (2 * STAV)           // 40960

extern __shared__ char dsm[];

__device__ __forceinline__ uint32_t smem_u32(const void* p) {
    uint32_t a;
    asm("{ .reg .u64 t; cvta.to.shared.u64 t, %1; cvt.u32.u64 %0, t; }"
        : "=r"(a) : "l"(p));
    return a;
}

#define CPA16(dst, src) \
    asm volatile("cp.async.cg.shared.global [%0], [%1], 16;" :: "r"(dst), "l"(src))
#define CPA_COMMIT() asm volatile("cp.async.commit_group;" ::: "memory")
#define CPA_WAIT0()  asm volatile("cp.async.wait_group 0;" ::: "memory")

#define LDSM4(R, addr)                                                        \
    asm volatile("ldmatrix.sync.aligned.m8n8.x4.shared.b16 {%0,%1,%2,%3}, [%4];" \
                 : "=r"((R)[0]), "=r"((R)[1]), "=r"((R)[2]), "=r"((R)[3])     \
                 : "r"(addr))

#define MMA(cc, A, b0, b1)                                                    \
    asm volatile("mma.sync.aligned.m16n8k16.row.col.f32.bf16.bf16.f32 "       \
                 "{%0,%1,%2,%3},{%4,%5,%6,%7},{%8,%9},{%0,%1,%2,%3};"         \
                 : "+f"((cc)[0]), "+f"((cc)[1]), "+f"((cc)[2]), "+f"((cc)[3]) \
                 : "r"((A)[0]), "r"((A)[1]), "r"((A)[2]), "r"((A)[3]),        \
                   "r"(b0), "r"(b1))

#define MMA_F16(cc, A, b0, b1)                                                \
    asm volatile("mma.sync.aligned.m16n8k16.row.col.f32.f16.f16.f32 "         \
                 "{%0,%1,%2,%3},{%4,%5,%6,%7},{%8,%9},{%0,%1,%2,%3};"         \
                 : "+f"((cc)[0]), "+f"((cc)[1]), "+f"((cc)[2]), "+f"((cc)[3]) \
                 : "r"((A)[0]), "r"((A)[1]), "r"((A)[2]), "r"((A)[3]),        \
                   "r"(b0), "r"(b1))

__device__ __forceinline__ uint32_t pk(bf16 a, bf16 b) {
    return (uint32_t)__bfloat16_as_ushort(a) | ((uint32_t)__bfloat16_as_ushort(b) << 16);
}

__device__ __forceinline__ uint32_t pkh(float a, float b) {
    __half2 h = __floats2half2_rn(a, b);
    return *(uint32_t*)&h;
}

__device__ __forceinline__ void split1(float v, bf16& h, bf16& l) {
    h = __float2bfloat16_rn(v);
    l = __float2bfloat16_rn(v - __bfloat162float(h));
}

// ---------------------------------------------------------------------------
// 3-term split-precision NT GEMM body (validated R7 structure).
// ---------------------------------------------------------------------------
__device__ __forceinline__
void gemm_body(const bf16* __restrict__ Ah, const bf16* __restrict__ Al,
               const bf16* __restrict__ Bh, const bf16* __restrict__ Bl,
               const float* __restrict__ bias,
               float* __restrict__ Cf, bf16* __restrict__ Ch, bf16* __restrict__ Cl,
               int M, int N, int K, int bm, int bn)
{
    const int tid  = threadIdx.x;
    const int wid  = tid >> 5;
    const int lane = tid & 31;
    const int wm   = wid >> 2;
    const int wn   = wid & 3;

    const int lrow  = tid >> 1;
    const int lsegB = (tid & 1) * 32;
    const uint32_t so = (uint32_t)lrow * ROWB + (uint32_t)lsegB;
    const bf16* pAh = Ah + (size_t)(bm + lrow) * K + lsegB / 2;
    const bf16* pAl = Al + (size_t)(bm + lrow) * K + lsegB / 2;
    const bf16* pBh = Bh + (size_t)(bn + lrow) * K + lsegB / 2;
    const bf16* pBl = Bl + (size_t)(bn + lrow) * K + lsegB / 2;

    const uint32_t sb = smem_u32(dsm);
    const uint32_t laneOff = (uint32_t)(lane & 15) * ROWB + (uint32_t)(lane >> 4) * 16;

    float acc[4][4][4] = {};

    {
        const uint32_t s0 = sb;
        CPA16(s0 + 0 * TILEB + so,      pAh);
        CPA16(s0 + 0 * TILEB + so + 16, pAh + 8);
        CPA16(s0 + 1 * TILEB + so,      pAl);
        CPA16(s0 + 1 * TILEB + so + 16, pAl + 8);
        CPA16(s0 + 2 * TILEB + so,      pBh);
        CPA16(s0 + 2 * TILEB + so + 16, pBh + 8);
        CPA16(s0 + 3 * TILEB + so,      pBl);
        CPA16(s0 + 3 * TILEB + so + 16, pBl + 8);
        CPA_COMMIT();
    }

    const int NC = K >> 5;
    for (int c = 0; c < NC; c++) {
        CPA_WAIT0();
        __syncthreads();

        if (c + 1 < NC) {
            const int k1 = (c + 1) << 5;
            const uint32_t s1 = sb + (uint32_t)((c + 1) & 1) * STAGE;
            CPA16(s1 + 0 * TILEB + so,      pAh + k1);
            CPA16(s1 + 0 * TILEB + so + 16, pAh + k1 + 8);
            CPA16(s1 + 1 * TILEB + so,      pAl + k1);
            CPA16(s1 + 1 * TILEB + so + 16, pAl + k1 + 8);
            CPA16(s1 + 2 * TILEB + so,      pBh + k1);
            CPA16(s1 + 2 * TILEB + so + 16, pBh + k1 + 8);
            CPA16(s1 + 3 * TILEB + so,      pBl + k1);
            CPA16(s1 + 3 * TILEB + so + 16, pBl + k1 + 8);
            CPA_COMMIT();
        }

        const uint32_t sbase = sb + (uint32_t)(c & 1) * STAGE;
        const uint32_t aH = sbase + 0 * TILEB + (uint32_t)wm * 64 * ROWB + laneOff;
        const uint32_t aL = aH + TILEB;
        const uint32_t bH = sbase + 2 * TILEB + (uint32_t)wn * 32 * ROWB + laneOff;
        const uint32_t bL = bH + TILEB;

        #pragma unroll
        for (int ks = 0; ks < 2; ks++) {
            const uint32_t ko = ks * 32;
            uint32_t a[4][4], bh[2][4], bl[2][4];
            LDSM4(bh[0], bH + ko);
            LDSM4(bh[1], bH + 16 * ROWB + ko);
            LDSM4(bl[0], bL + ko);
            LDSM4(bl[1], bL + 16 * ROWB + ko);
            #pragma unroll
            for (int mt = 0; mt < 4; mt++) LDSM4(a[mt], aH + mt * 16 * ROWB + ko);

            #pragma unroll
            for (int mt = 0; mt < 4; mt++)
                #pragma unroll
                for (int nt = 0; nt < 4; nt++)
                    MMA(acc[mt][nt], a[mt], bh[nt >> 1][nt & 1], bh[nt >> 1][(nt & 1) + 2]);
            #pragma unroll
            for (int mt = 0; mt < 4; mt++)
                #pragma unroll
                for (int nt = 0; nt < 4; nt++)
                    MMA(acc[mt][nt], a[mt], bl[nt >> 1][nt & 1], bl[nt >> 1][(nt & 1) + 2]);

            #pragma unroll
            for (int mt = 0; mt < 4; mt++) LDSM4(a[mt], aL + mt * 16 * ROWB + ko);
            #pragma unroll
            for (int mt = 0; mt < 4; mt++)
                #pragma unroll
                for (int nt = 0; nt < 4; nt++)
                    MMA(acc[mt][nt], a[mt], bh[nt >> 1][nt & 1], bh[nt >> 1][(nt & 1) + 2]);
        }
    }

    const int lr = lane >> 2;
    const int lc = (lane & 3) * 2;
    #pragma unroll
    for (int mt = 0; mt < 4; mt++) {
        const int m0 = bm + wm * 64 + mt * 16 + lr;
        #pragma unroll
        for (int nt = 0; nt < 4; nt++) {
            const int n0 = bn + wn * 32 + nt * 8 + lc;
            float bx = 0.f, by = 0.f;
            if (bias) { bx = bias[n0]; by = bias[n0 + 1]; }
            float v00 = acc[mt][nt][0] + bx, v01 = acc[mt][nt][1] + by;
            float v10 = acc[mt][nt][2] + bx, v11 = acc[mt][nt][3] + by;
            if (Cf) {
                *(float2*)(Cf + (size_t)m0 * N + n0)       = make_float2(v00, v01);
                *(float2*)(Cf + (size_t)(m0 + 8) * N + n0) = make_float2(v10, v11);
            } else {
                bf16 h0, h1, l0, l1;
                split1(v00, h0, l0); split1(v01, h1, l1);
                *(uint32_t*)(Ch + (size_t)m0 * N + n0) = pk(h0, h1);
                *(uint32_t*)(Cl + (size_t)m0 * N + n0) = pk(l0, l1);
                split1(v10, h0, l0); split1(v11, h1, l1);
                *(uint32_t*)(Ch + (size_t)(m0 + 8) * N + n0) = pk(h0, h1);
                *(uint32_t*)(Cl + (size_t)(m0 + 8) * N + n0) = pk(l0, l1);
            }
        }
    }
}

// Batched QK^T GEMM -> fp32 scores.
__global__ __launch_bounds__(256, 2)
void gemm_sp(const bf16* __restrict__ Ah, const bf16* __restrict__ Al,
             const bf16* __restrict__ Bh, const bf16* __restrict__ Bl,
             float* __restrict__ Cf,
             int M, int N, int K, size_t sA, size_t sB, size_t sC)
{
    const size_t zA = (size_t)blockIdx.z * sA;
    const size_t zB = (size_t)blockIdx.z * sB;
    const size_t zC = (size_t)blockIdx.z * sC;
    gemm_body(Ah + zA, Al + zA, Bh + zB, Bl + zB, nullptr,
              Cf + zC, nullptr, nullptr,
              M, N, K, blockIdx.y * 128, blockIdx.x * 128);
}

// Fused Q/K projection: z selects {Q, K} (split bf16 outputs).
__global__ __launch_bounds__(256, 2)
void gemm_qkv(const bf16* __restrict__ xh, const bf16* __restrict__ xl,
              const bf16* __restrict__ Wqh, const bf16* __restrict__ Wql,
              const bf16* __restrict__ Wkh, const bf16* __restrict__ Wkl,
              const float* __restrict__ bq, const float* __restrict__ bk,
              bf16* __restrict__ Qh, bf16* __restrict__ Ql,
              bf16* __restrict__ Kh, bf16* __restrict__ Kl)
{
    const bf16 *Bh, *Bl; const float* bias; bf16 *Ch, *Cl;
    if (blockIdx.z == 0) { Bh = Wqh; Bl = Wql; bias = bq; Ch = Qh; Cl = Ql; }
    else                 { Bh = Wkh; Bl = Wkl; bias = bk; Ch = Kh; Cl = Kl; }
    gemm_body(xh, xl, Bh, Bl, bias, nullptr, Ch, Cl,
              BATCH * SEQ, DIM, DIM, blockIdx.y * 128, blockIdx.x * 128);
}

// ---------------------------------------------------------------------------
// Single-term fp16 NT GEMM: C[M,N] = scale * (A[M,K] * B[N,K]^T) (+ bias).
// ---------------------------------------------------------------------------
__global__ __launch_bounds__(256, 2)
void gemm_h16(const __half* __restrict__ A, const __half* __restrict__ B,
              const float* __restrict__ bias,
              float* __restrict__ Cf, __half* __restrict__ C16, float scale,
              int M, int N, int K, size_t sA, size_t sB, size_t sC)
{
    const __half* Az = A + (size_t)blockIdx.z * sA;
    const __half* Bz = B + (size_t)blockIdx.z * sB;
    const size_t  zC = (size_t)blockIdx.z * sC;

    const int tid  = threadIdx.x;
    const int wid  = tid >> 5;
    const int lane = tid & 31;
    const int wm   = wid >> 2;
    const int wn   = wid & 3;
    const int bm = blockIdx.y * 128;
    const int bn = blockIdx.x * 128;

    const int lrow  = tid >> 1;
    const int lsegB = (tid & 1) * 32;
    const uint32_t so = (uint32_t)lrow * ROWB + (uint32_t)lsegB;
    const __half* pA = Az + (size_t)(bm + lrow) * K + lsegB / 2;
    const __half* pB = Bz + (size_t)(bn + lrow) * K + lsegB / 2;

    const uint32_t sb = smem_u32(dsm);
    const uint32_t laneOff = (uint32_t)(lane & 15) * ROWB + (uint32_t)(lane >> 4) * 16;

    float acc[4][4][4] = {};

    {
        CPA16(sb + so,              pA);
        CPA16(sb + so + 16,         pA + 8);
        CPA16(sb + TILEB + so,      pB);
        CPA16(sb + TILEB + so + 16, pB + 8);
        CPA_COMMIT();
    }

    const int NC = K >> 5;
    for (int c = 0; c < NC; c++) {
        CPA_WAIT0();
        __syncthreads();

        if (c + 1 < NC) {
            const int k1 = (c + 1) << 5;
            const uint32_t s1 = sb + (uint32_t)((c + 1) & 1) * STAV;
            CPA16(s1 + so,              pA + k1);
            CPA16(s1 + so + 16,         pA + k1 + 8);
            CPA16(s1 + TILEB + so,      pB + k1);
            CPA16(s1 + TILEB + so + 16, pB + k1 + 8);
            CPA_COMMIT();
        }

        const uint32_t sbase = sb + (uint32_t)(c & 1) * STAV;
        const uint32_t aB = sbase + (uint32_t)wm * 64 * ROWB + laneOff;
        const uint32_t bB = sbase + TILEB + (uint32_t)wn * 32 * ROWB + laneOff;

        #pragma unroll
        for (int ks = 0; ks < 2; ks++) {
            const uint32_t ko = ks * 32;
            uint32_t a[4][4], b[2][4];
            LDSM4(b[0], bB + ko);
            LDSM4(b[1], bB + 16 * ROWB + ko);
            #pragma unroll
            for (int mt = 0; mt < 4; mt++) LDSM4(a[mt], aB + mt * 16 * ROWB + ko);
            #pragma unroll
            for (int mt = 0; mt < 4; mt++)
                #pragma unroll
                for (int nt = 0; nt < 4; nt++)
                    MMA_F16(acc[mt][nt], a[mt], b[nt >> 1][nt & 1], b[nt >> 1][(nt & 1) + 2]);
        }
    }

    const int lr = lane >> 2;
    const int lc = (lane & 3) * 2;
    #pragma unroll
    for (int mt = 0; mt < 4; mt++) {
        const int m0 = bm + wm * 64 + mt * 16 + lr;
        #pragma unroll
        for (int nt = 0; nt < 4; nt++) {
            const int n0 = bn + wn * 32 + nt * 8 + lc;
            float bx = 0.f, by = 0.f;
            if (bias) { bx = bias[n0]; by = bias[n0 + 1]; }
            float v00 = acc[mt][nt][0] * scale + bx, v01 = acc[mt][nt][1] * scale + by;
            float v10 = acc[mt][nt][2] * scale + bx, v11 = acc[mt][nt][3] * scale + by;
            if (Cf) {
                *(float2*)(Cf + zC + (size_t)m0 * N + n0)       = make_float2(v00, v01);
                *(float2*)(Cf + zC + (size_t)(m0 + 8) * N + n0) = make_float2(v10, v11);
            } else {
                *(uint32_t*)(C16 + zC + (size_t)m0 * N + n0)       = pkh(v00, v01);
                *(uint32_t*)(C16 + zC + (size_t)(m0 + 8) * N + n0) = pkh(v10, v11);
            }
        }
    }
}

// ---------------------------------------------------------------------------
// Merged fp32 conversions, LOAD-BALANCED across z:
//   z in {0..3}: x quarter -> (xh, xl, xf) in one pass (x read once)
//   z = 4: Wq -> hi/lo;  z = 5: Wk -> hi/lo;  z = 6: Wv -> fp16
// ---------------------------------------------------------------------------
__global__ __launch_bounds__(256)
void split_all(const float* __restrict__ x,  const float* __restrict__ Wq,
               const float* __restrict__ Wk, const float* __restrict__ Wv,
               bf16* __restrict__ xh,  bf16* __restrict__ xl, __half* __restrict__ xf,
               bf16* __restrict__ Wqh, bf16* __restrict__ Wql,
               bf16* __restrict__ Wkh, bf16* __restrict__ Wkl,
               __half* __restrict__ Wvf)
{
    const int z = blockIdx.z;
    if (z < 4) {
        const size_t base = (size_t)z * (NX / 16);  // quarter of x, in float4s
        const size_t n4   = NX / 16;
        for (size_t i = (size_t)blockIdx.x * blockDim.x + threadIdx.x; i < n4;
             i += (size_t)gridDim.x * blockDim.x) {
            const size_t j = base + i;
            float4 v = ((const float4*)x)[j];
            bf16 h0, h1, h2, h3, l0, l1, l2, l3;
            split1(v.x, h0, l0); split1(v.y, h1, l1);
            split1(v.z, h2, l2); split1(v.w, h3, l3);
            ((uint2*)xh)[j] = make_uint2(pk(h0, h1), pk(h2, h3));
            ((uint2*)xl)[j] = make_uint2(pk(l0, l1), pk(l2, l3));
            ((uint2*)xf)[j] = make_uint2(pkh(v.x, v.y), pkh(v.z, v.w));
        }
        return;
    }
    if (z == 6) {
        for (size_t i = (size_t)blockIdx.x * blockDim.x + threadIdx.x; i < NW / 4;
             i += (size_t)gridDim.x * blockDim.x) {
            float4 v = ((const float4*)Wv)[i];
            ((uint2*)Wvf)[i] = make_uint2(pkh(v.x, v.y), pkh(v.z, v.w));
        }
        return;
    }
    const float* in; bf16 *hi, *lo;
    if (z == 4) { in = Wq; hi = Wqh; lo = Wql; }
    else        { in = Wk; hi = Wkh; lo = Wkl; }
    for (size_t i = (size_t)blockIdx.x * blockDim.x + threadIdx.x; i < NW / 4;
         i += (size_t)gridDim.x * blockDim.x) {
        float4 v = ((const float4*)in)[i];
        bf16 h0, h1, h2, h3, l0, l1, l2, l3;
        split1(v.x, h0, l0); split1(v.y, h1, l1);
        split1(v.z, h2, l2); split1(v.w, h3, l3);
        ((uint2*)hi)[i] = make_uint2(pk(h0, h1), pk(h2, h3));
        ((uint2*)lo)[i] = make_uint2(pk(l0, l1), pk(l2, l3));
    }
}

// ---------------------------------------------------------------------------
// fp16 transpose (z = batch): Vt[b][d][s] = V[b][s][d]
// ---------------------------------------------------------------------------
__global__ __launch_bounds__(256)
void transpose_vf(const __half* __restrict__ V, __half* __restrict__ Vt)
{
    __shared__ __half t[32][33];
    const int b  = blockIdx.z;
    const __half* src = V  + (size_t)b * SEQ * DIM;
    __half*       dst = Vt + (size_t)b * SEQ * DIM;
    const int d0 = blockIdx.x * 32;
    const int s0 = blockIdx.y * 32;
    const int tx = threadIdx.x;
    const int ty = threadIdx.y;
    #pragma unroll
    for (int j = 0; j < 32; j += 8)
        t[ty + j][tx] = src[(size_t)(s0 + ty + j) * DIM + d0 + tx];
    __syncthreads();
    #pragma unroll
    for (int j = 0; j < 32; j += 8)
        dst[(size_t)(d0 + ty + j) * SEQ + s0 + tx] = t[tx][ty + j];
}

// ---------------------------------------------------------------------------
// Warp-per-row softmax over SEQ=2048 -> fp16 probabilities (UNscaled).
// 8 warps/block, 1 row/warp: 16 float4/lane (MLP=16), shfl-only reductions.
// ---------------------------------------------------------------------------
__global__ __launch_bounds__(256)
void softmax_f16(const float* __restrict__ S, __half* __restrict__ Pf)
{
    const int wid  = threadIdx.x >> 5;
    const int lane = threadIdx.x & 31;
    const size_t row = (size_t)blockIdx.x * 8 + wid;
    const float* rp = S + row * SEQ;

    float4 v[16];
    #pragma unroll
    for (int i = 0; i < 16; i++)
        v[i] = *(const float4*)(rp + ((size_t)(i * 32 + lane)) * 4);

    float m = -3.4e38f;
    #pragma unroll
    for (int i = 0; i < 16; i++)
        m = fmaxf(m, fmaxf(fmaxf(v[i].x, v[i].y), fmaxf(v[i].z, v[i].w)));
    #pragma unroll
    for (int o = 16; o > 0; o >>= 1)
        m = fmaxf(m, __shfl_xor_sync(0xffffffffu, m, o));

    float s = 0.f;
    #pragma unroll
    for (int i = 0; i < 16; i++) {
        v[i].x = __expf(v[i].x - m); v[i].y = __expf(v[i].y - m);
        v[i].z = __expf(v[i].z - m); v[i].w = __expf(v[i].w - m);
        s += (v[i].x + v[i].y) + (v[i].z + v[i].w);
    }
    #pragma unroll
    for (int o = 16; o > 0; o >>= 1)
        s += __shfl_xor_sync(0xffffffffu, s, o);

    const float scale = 1.0f / s;      // NORM_FACT applied in AV epilogue
    __half* ph = Pf + row * SEQ;
    #pragma unroll
    for (int i = 0; i < 16; i++) {
        *(uint2*)(ph + ((size_t)(i * 32 + lane)) * 4) =
            make_uint2(pkh(v[i].x * scale, v[i].y * scale),
                       pkh(v[i].z * scale, v[i].w * scale));
    }
}

// ---------------------------------------------------------------------------
extern "C" void kernel_launch(void* const* d_in, const int* in_sizes, int n_in,
                              void* d_out, int out_size)
{
    const float* x  = (const float*)d_in[0];
    const float* Wq = (const float*)d_in[1];
    const float* bq = (const float*)d_in[2];
    const float* Wk = (const float*)d_in[3];
    const float* bk = (const float*)d_in[4];
    const float* Wv = (const float*)d_in[5];
    const float* bv = (const float*)d_in[6];
    float* out = (float*)d_out;

    bf16 *xh, *xl, *Wqh, *Wql, *Wkh, *Wkl;
    bf16 *Qh, *Ql, *Kh, *Kl;
    __half *xf, *Wvf, *Vf, *Vtf, *Pf;
    float* P;
    cudaGetSymbolAddress((void**)&xh,  g_xh);  cudaGetSymbolAddress((void**)&xl,  g_xl);
    cudaGetSymbolAddress((void**)&Wqh, g_Wqh); cudaGetSymbolAddress((void**)&Wql, g_Wql);
    cudaGetSymbolAddress((void**)&Wkh, g_Wkh); cudaGetSymbolAddress((void**)&Wkl, g_Wkl);
    cudaGetSymbolAddress((void**)&Qh,  g_Qh);  cudaGetSymbolAddress((void**)&Ql,  g_Ql);
    cudaGetSymbolAddress((void**)&Kh,  g_Kh);  cudaGetSymbolAddress((void**)&Kl,  g_Kl);
    cudaGetSymbolAddress((void**)&xf,  g_xf);
    cudaGetSymbolAddress((void**)&Wvf, g_Wvf);
    cudaGetSymbolAddress((void**)&Vf,  g_Vf);
    cudaGetSymbolAddress((void**)&Vtf, g_Vtf);
    cudaGetSymbolAddress((void**)&Pf,  g_Pf);
    cudaGetSymbolAddress((void**)&P,   g_P);

    cudaFuncSetAttribute(gemm_sp,  cudaFuncAttributeMaxDynamicSharedMemorySize, SMEM_TOTAL);
    cudaFuncSetAttribute(gemm_qkv, cudaFuncAttributeMaxDynamicSharedMemorySize, SMEM_TOTAL);
    cudaFuncSetAttribute(gemm_h16, cudaFuncAttributeMaxDynamicSharedMemorySize, SMEM_AV);

    // One-time side stream + events (host resources, no device memory).
    static cudaStream_t s1 = nullptr;
    static cudaEvent_t eFork = nullptr, eJoin = nullptr;
    if (!s1) {
        cudaStreamCreateWithFlags(&s1, cudaStreamNonBlocking);
        cudaEventCreateWithFlags(&eFork, cudaEventDisableTiming);
        cudaEventCreateWithFlags(&eJoin, cudaEventDisableTiming);
    }

    // 0) conversions: x -> (bf16 hi/lo + fp16) in one pass, Wq/Wk -> hi/lo,
    //    Wv -> fp16. Balanced z-slices (x quartered).
    {
        dim3 grid(1024, 1, 7);
        split_all<<<grid, 256>>>(x, Wq, Wk, Wv, xh, xl, xf,
                                 Wqh, Wql, Wkh, Wkl, Wvf);
    }

    // Fork: side stream handles the V pipeline (independent of Q/K chain).
    cudaEventRecord(eFork, 0);
    cudaStreamWaitEvent(s1, eFork, 0);

    // 1a) Q/K projections (main stream, 3-term split path)
    {
        dim3 grid(DIM / 128, (BATCH * SEQ) / 128, 2);
        gemm_qkv<<<grid, 256, SMEM_TOTAL>>>(xh, xl, Wqh, Wql, Wkh, Wkl,
                                            bq, bk, Qh, Ql, Kh, Kl);
    }

    // 1b) V projection + transpose on side stream (overlaps Q/K proj + QK)
    {
        dim3 grid(DIM / 128, (BATCH * SEQ) / 128, 1);
        gemm_h16<<<grid, 256, SMEM_AV, s1>>>(xf, Wvf, bv, nullptr, Vf, 1.0f,
                                             BATCH * SEQ, DIM, DIM, 0, 0, 0);
        dim3 tgrid(DIM / 32, SEQ / 32, BATCH);
        transpose_vf<<<tgrid, dim3(32, 8), 0, s1>>>(Vf, Vtf);
        cudaEventRecord(eJoin, s1);
    }

    // 3) scores[b] = Q[b] @ K[b]^T  -> fp32 P (3-term split path)
    {
        dim3 grid(SEQ / 128, SEQ / 128, BATCH);
        gemm_sp<<<grid, 256, SMEM_TOTAL>>>(Qh, Ql, Kh, Kl, P,
                                           SEQ, SEQ, DIM,
                                           (size_t)SEQ * DIM, (size_t)SEQ * DIM,
                                           (size_t)SEQ * SEQ);
    }

    // 4) softmax rows -> fp16 P (unscaled), warp-per-row
    softmax_f16<<<(BATCH * SEQ) / 8, 256>>>(P, Pf);

    // Join: AV needs Vtf from the side stream.
    cudaStreamWaitEvent(0, eJoin, 0);

    // 5) out[b] = NORM * (P[b] @ Vt[b]^T)  (single-term fp16 MMA)
    {
        dim3 grid(DIM / 128, SEQ / 128, BATCH);
        gemm_h16<<<grid, 256, SMEM_AV>>>(Pf, Vtf, nullptr, out, nullptr, NORM_FACT,
                                         SEQ, DIM, SEQ,
                                         (size_t)SEQ * SEQ, (size_t)SEQ * DIM,
                                         (size_t)SEQ * DIM);
    }
}